// round 9
// baseline (speedup 1.0000x reference)
#include <cuda_runtime.h>
#include <math.h>
#include <stdint.h>

// Problem constants
#define Bn 16
#define Nn 1024
#define Dn 256
#define Hn 128
#define Sn 12     // MAX_CLUSTERS
#define CSn 16    // CSIZE
#define NEGV (-1e9f)

#define PARTITIONABLE 1

// ---------------- scratch ----------------
__device__ float g_XW1[Bn * Nn * Hn];       // [b][n][j] = x@W1[:256] + b1
__device__ float g_W1cT[Hn * Hn];           // [j][k] = W1[256+k][j]
__device__ float g_xpart[Bn][8][Dn];        // partial column sums of x

// ---------------- Threefry2x32 (JAX-exact) ----------------
__device__ __forceinline__ uint2 tf2x32(unsigned k0, unsigned k1, unsigned x0, unsigned x1) {
    unsigned ks2 = k0 ^ k1 ^ 0x1BD11BDAu;
    x0 += k0; x1 += k1;
#define TFR(r) { x0 += x1; x1 = (x1 << (r)) | (x1 >> (32 - (r))); x1 ^= x0; }
    TFR(13) TFR(15) TFR(26) TFR(6)   x0 += k1;  x1 += ks2 + 1u;
    TFR(17) TFR(29) TFR(16) TFR(24)  x0 += ks2; x1 += k0 + 2u;
    TFR(13) TFR(15) TFR(26) TFR(6)   x0 += k0;  x1 += k1 + 3u;
    TFR(17) TFR(29) TFR(16) TFR(24)  x0 += k1;  x1 += ks2 + 4u;
    TFR(13) TFR(15) TFR(26) TFR(6)   x0 += ks2; x1 += k0 + 5u;
#undef TFR
    return make_uint2(x0, x1);
}

struct P2 { unsigned x, y; };
constexpr unsigned rotl_c(unsigned x, int r) { return (x << r) | (x >> (32 - r)); }
constexpr P2 tf_c(unsigned k0, unsigned k1, unsigned x0, unsigned x1) {
    unsigned ks2 = k0 ^ k1 ^ 0x1BD11BDAu;
    x0 += k0; x1 += k1;
    const int R0[4] = {13, 15, 26, 6};
    const int R1[4] = {17, 29, 16, 24};
    for (int i = 0; i < 5; i++) {
        for (int j = 0; j < 4; j++) {
            int r = (i % 2 == 0) ? R0[j] : R1[j];
            x0 += x1; x1 = rotl_c(x1, r); x1 ^= x0;
        }
        int a = (i + 1) % 3, bsel = (i + 2) % 3;
        unsigned inj0 = (a == 0) ? k0 : ((a == 1) ? k1 : ks2);
        unsigned inj1 = (bsel == 0) ? k0 : ((bsel == 1) ? k1 : ks2);
        x0 += inj0; x1 += inj1 + (unsigned)(i + 1);
    }
    return P2{x0, x1};
}

struct KeyTab { unsigned a[Sn * CSn]; unsigned b[Sn * CSn]; };
constexpr KeyTab mk_keys() {
    KeyTab t{};
    unsigned k0 = 0u, k1 = 42u;
    for (int i = 0; i < Sn * CSn; i++) {
#if PARTITIONABLE
        P2 nk = tf_c(k0, k1, 0u, 0u);
        P2 sk = tf_c(k0, k1, 0u, 1u);
        t.a[i] = sk.x; t.b[i] = sk.y;
        k0 = nk.x; k1 = nk.y;
#else
        P2 l0 = tf_c(k0, k1, 0u, 2u);
        P2 l1 = tf_c(k0, k1, 1u, 3u);
        t.a[i] = l0.y; t.b[i] = l1.y;
        k0 = l0.x; k1 = l1.x;
#endif
    }
    return t;
}
static constexpr KeyTab H_KEYS = mk_keys();
__constant__ KeyTab SELKEYS = H_KEYS;

__device__ __forceinline__ unsigned rand_bits(unsigned k0, unsigned k1, unsigned g) {
#if PARTITIONABLE
    uint2 o = tf2x32(k0, k1, 0u, g);
    return o.x ^ o.y;
#else
    const unsigned m = (Bn * Nn) / 2;
    if (g < m) { uint2 o = tf2x32(k0, k1, g, g + m); return o.x; }
    else       { uint2 o = tf2x32(k0, k1, g - m, g); return o.y; }
#endif
}

__device__ __forceinline__ float gumbel_val(unsigned k0, unsigned k1, int b, int node,
                                            float logit) {
    unsigned bits = rand_bits(k0, k1, (unsigned)((b << 10) + node));
    float u = __uint_as_float((bits >> 9) | 0x3f800000u) - 1.0f;
    float s1 = u + 1e-8f;
    float l1 = __logf(s1);
    float s2 = (-l1) + 1e-8f;
    float l2 = __logf(s2);
    return logit + (-l2);
}

__device__ __forceinline__ unsigned long long packkey(float val, int node) {
    unsigned ub = __float_as_uint(val);
    unsigned ord = (ub & 0x80000000u) ? ~ub : (ub | 0x80000000u);
    return (((unsigned long long)ord) << 32) | (unsigned)(0xFFFFFFFFu - node);
}

__device__ __forceinline__ float sigm(float v) {
    return 0.5f * tanhf(0.5f * v) + 0.5f;
}

// ---------------- Kernel 1: tiled SGEMM, output [b][n][j] ----------------
__global__ void __launch_bounds__(256) k_xw1(const float* __restrict__ x,
                                             const float* __restrict__ W1,
                                             const float* __restrict__ b1) {
    __shared__ float xs[64][33];
    __shared__ float ws[32][128];
    int tile = blockIdx.x;
    int b = blockIdx.y;
    int t = threadIdx.x;
    int n0 = tile * 64;
    int nl = t & 63;
    int jbase = (t >> 6) * 32;

    float acc[32];
#pragma unroll
    for (int i = 0; i < 32; i++) acc[i] = 0.f;

    for (int k0 = 0; k0 < Dn; k0 += 32) {
        for (int i = t; i < 64 * 32; i += 256) {
            int nn = i >> 5, kk = i & 31;
            xs[nn][kk] = x[((b << 10) + n0 + nn) * Dn + k0 + kk];
        }
        for (int i = t; i < 32 * 128; i += 256) {
            int kk = i >> 7, jj = i & 127;
            ws[kk][jj] = W1[(k0 + kk) * Hn + jj];
        }
        __syncthreads();
#pragma unroll 4
        for (int k = 0; k < 32; k++) {
            float xv = xs[nl][k];
            const float4* w4 = reinterpret_cast<const float4*>(&ws[k][jbase]);
#pragma unroll
            for (int i = 0; i < 8; i++) {
                float4 w = w4[i];
                acc[4 * i + 0] = fmaf(xv, w.x, acc[4 * i + 0]);
                acc[4 * i + 1] = fmaf(xv, w.y, acc[4 * i + 1]);
                acc[4 * i + 2] = fmaf(xv, w.z, acc[4 * i + 2]);
                acc[4 * i + 3] = fmaf(xv, w.w, acc[4 * i + 3]);
            }
        }
        __syncthreads();
    }
#pragma unroll
    for (int i = 0; i < 32; i++) {
        int j = jbase + i;
        g_XW1[(((b << 10) + n0 + nl) << 7) + j] = acc[i] + b1[j];
    }
}

// ---------------- Kernel 2: transpose ctx block of W1 -> [j][k] ----------------
__global__ void k_w1ct(const float* __restrict__ W1) {
    int idx = blockIdx.x * blockDim.x + threadIdx.x;
    if (idx < Hn * Hn) {
        int j = idx >> 7, k = idx & 127;
        g_W1cT[idx] = W1[(Dn + k) * Hn + j];
    }
}

// ---------------- Kernel 3: xmean partials (deterministic) ----------------
__global__ void __launch_bounds__(256) k_xmean(const float* __restrict__ x) {
    int b = blockIdx.x, p = blockIdx.y;   // 16 x 8
    int t = threadIdx.x;                  // column 0..255
    const float* px = x + (((long)(b) << 10) + p * 128) * Dn + t;
    float a0 = 0.f, a1 = 0.f, a2 = 0.f, a3 = 0.f, a4 = 0.f, a5 = 0.f, a6 = 0.f, a7 = 0.f;
    for (int m = 0; m < 128; m += 8) {
        a0 += px[(m + 0) * Dn]; a1 += px[(m + 1) * Dn];
        a2 += px[(m + 2) * Dn]; a3 += px[(m + 3) * Dn];
        a4 += px[(m + 4) * Dn]; a5 += px[(m + 5) * Dn];
        a6 += px[(m + 6) * Dn]; a7 += px[(m + 7) * Dn];
    }
    g_xpart[b][p][t] = ((a0 + a1) + (a2 + a3)) + ((a4 + a5) + (a6 + a7));
}

#define BAR768() asm volatile("bar.sync 1, 768;" ::: "memory")

// ---------------- Main kernel (v6: contiguous per-thread weight streams) ----------------
__global__ void __launch_bounds__(1024) k_main(
    const float* __restrict__ x, const float* __restrict__ adj,
    const float* __restrict__ Wih, const float* __restrict__ Whh,
    const float* __restrict__ W2, const float* __restrict__ b2,
    const float* __restrict__ bih, const float* __restrict__ bhh,
    const float* __restrict__ Wc, const float* __restrict__ bc,
    float* __restrict__ out) {
    int b = blockIdx.x;
    int n = threadIdx.x;
    int lane = n & 31, wid = n >> 5;

    __shared__ float s_logit[Nn];
    __shared__ float s_ctx[Hn], s_gctx[Hn], s_hidden[Hn];
    __shared__ float s_part[768];
    __shared__ float s_gi[Sn][3 * Hn];
    __shared__ float s_emb[Dn];
    __shared__ float s_w2[Hn];
    __shared__ unsigned char s_avail[Nn], s_mem[Nn], s_kmask[Nn];
    __shared__ int s_clist[Nn];
    __shared__ int s_flist[Nn];
    __shared__ int s_fcnt;
    __shared__ unsigned long long s_red[32];
    __shared__ int s_mlist[CSn + 1];
    __shared__ int s_mcnt;

    s_avail[n] = 1;
    if (n < Dn) {
        float s = ((g_xpart[b][0][n] + g_xpart[b][1][n]) + (g_xpart[b][2][n] + g_xpart[b][3][n]))
                + ((g_xpart[b][4][n] + g_xpart[b][5][n]) + (g_xpart[b][6][n] + g_xpart[b][7][n]));
        s_emb[n] = s / 1024.0f;
    }
    if (n < Hn) s_w2[n] = W2[n];
    __syncthreads();
    if (n < Hn) {
        float a0 = 0.f, a1 = 0.f, a2 = 0.f, a3 = 0.f;
        for (int d = 0; d < Dn; d += 4) {
            a0 = fmaf(s_emb[d + 0], Wc[(d + 0) * Hn + n], a0);
            a1 = fmaf(s_emb[d + 1], Wc[(d + 1) * Hn + n], a1);
            a2 = fmaf(s_emb[d + 2], Wc[(d + 2) * Hn + n], a2);
            a3 = fmaf(s_emb[d + 3], Wc[(d + 3) * Hn + n], a3);
        }
        s_gctx[n] = bc[n] + ((a0 + a1) + (a2 + a3));
        s_hidden[n] = 0.f;
    }
    float b2v = b2[0];
    __syncthreads();

    float* out_cf = out;                       // [16][12][256]
    float* out_ca = out + Bn * Sn * Dn;        // [16][12][12]
    float* out_as = out_ca + Bn * Sn * Sn;     // [16][1024][12]

    const float* arow = adj + ((long)b << 20);

    for (int c = 0; c < Sn; c++) {
        s_mem[n] = 0;
        if (n == 0) s_fcnt = 0;
        // ctx partials: 512 threads, 4 parts x 32 k, contiguous g_W1cT rows
        if (n < 512) {
            int p = n >> 7, j = n & 127;
            const float4* w4 = reinterpret_cast<const float4*>(g_W1cT + (j << 7) + p * 32);
            float a0 = 0.f, a1 = 0.f, a2 = 0.f, a3 = 0.f;
#pragma unroll
            for (int k = 0; k < 32; k += 4) {
                float4 v = w4[k >> 2];
                a0 = fmaf(s_gctx[p * 32 + k + 0], v.x, a0);
                a1 = fmaf(s_gctx[p * 32 + k + 1], v.y, a1);
                a2 = fmaf(s_gctx[p * 32 + k + 2], v.z, a2);
                a3 = fmaf(s_gctx[p * 32 + k + 3], v.w, a3);
            }
            s_part[p * 128 + j] = (a0 + a1) + (a2 + a3);
        }
        __syncthreads();
        if (n < Hn)
            s_ctx[n] = (s_part[n] + s_part[128 + n]) + (s_part[256 + n] + s_part[384 + n]);
        __syncthreads();

        // logits: relu(XW1[n][:] + ctx) @ W2 + b2 — contiguous float4 row
        float mylogit;
        {
            const float4* px4 = reinterpret_cast<const float4*>(
                g_XW1 + (((long)(b) << 10) + n) * Hn);
            float a0 = 0.f, a1 = 0.f, a2 = 0.f, a3 = 0.f,
                  a4 = 0.f, a5 = 0.f, a6 = 0.f, a7 = 0.f;
#pragma unroll 8
            for (int k = 0; k < Hn; k += 8) {
                float4 v0 = px4[k >> 2], v1 = px4[(k >> 2) + 1];
                a0 = fmaf(fmaxf(v0.x + s_ctx[k + 0], 0.f), s_w2[k + 0], a0);
                a1 = fmaf(fmaxf(v0.y + s_ctx[k + 1], 0.f), s_w2[k + 1], a1);
                a2 = fmaf(fmaxf(v0.z + s_ctx[k + 2], 0.f), s_w2[k + 2], a2);
                a3 = fmaf(fmaxf(v0.w + s_ctx[k + 3], 0.f), s_w2[k + 3], a3);
                a4 = fmaf(fmaxf(v1.x + s_ctx[k + 4], 0.f), s_w2[k + 4], a4);
                a5 = fmaf(fmaxf(v1.y + s_ctx[k + 5], 0.f), s_w2[k + 5], a5);
                a6 = fmaf(fmaxf(v1.z + s_ctx[k + 6], 0.f), s_w2[k + 6], a6);
                a7 = fmaf(fmaxf(v1.w + s_ctx[k + 7], 0.f), s_w2[k + 7], a7);
            }
            mylogit = (((a0 + a1) + (a2 + a3)) + ((a4 + a5) + (a6 + a7))) + b2v;
            s_logit[n] = mylogit;
        }

        // seed selection
        {
            unsigned k0 = SELKEYS.a[c * CSn + 0], k1 = SELKEYS.b[c * CSn + 0];
            float val = NEGV;
            if (s_avail[n]) val = gumbel_val(k0, k1, b, n, mylogit);
            unsigned long long pk = packkey(val, n);
            for (int off = 16; off; off >>= 1) {
                unsigned long long o = __shfl_down_sync(0xffffffffu, pk, off);
                if (o > pk) pk = o;
            }
            if (lane == 0) s_red[wid] = pk;
        }
        __syncthreads();
        int sel, valid;
        {
            unsigned long long v2 = s_red[lane];
            for (int off = 16; off; off >>= 1) {
                unsigned long long o = __shfl_down_sync(0xffffffffu, v2, off);
                if (o > v2) v2 = o;
            }
            v2 = __shfl_sync(0xffffffffu, v2, 0);
            sel = (int)(0xFFFFFFFFu - (unsigned)(v2 & 0xFFFFFFFFu));
            unsigned ordv = (unsigned)(v2 >> 32);
            unsigned fb = (ordv & 0x80000000u) ? (ordv ^ 0x80000000u) : ~ordv;
            valid = (__uint_as_float(fb) > -1e8f) ? 1 : 0;
        }
        if (valid && n == sel) { s_avail[n] = 0; s_mem[n] = 1; }
        if (n == 0) {
            s_mcnt = valid ? 1 : 0;
            if (valid) s_mlist[0] = sel;
        }

        // ---- 2-hop BFS ----
        bool nb1 = (arow[(sel << 10) + n] != 0.0f);
        bool reach1 = (n == sel) || nb1;
        if (nb1 && n != sel) { int p = atomicAdd(&s_fcnt, 1); s_flist[p] = n; }
        __syncthreads();
        {
            int fc = s_fcnt;
            bool rr = false;
            int f = 0;
            for (; f + 8 <= fc; f += 8) {
                float a0 = arow[(s_flist[f + 0] << 10) + n];
                float a1 = arow[(s_flist[f + 1] << 10) + n];
                float a2 = arow[(s_flist[f + 2] << 10) + n];
                float a3 = arow[(s_flist[f + 3] << 10) + n];
                float a4 = arow[(s_flist[f + 4] << 10) + n];
                float a5 = arow[(s_flist[f + 5] << 10) + n];
                float a6 = arow[(s_flist[f + 6] << 10) + n];
                float a7 = arow[(s_flist[f + 7] << 10) + n];
                rr = rr | (a0 != 0.f) | (a1 != 0.f) | (a2 != 0.f) | (a3 != 0.f)
                        | (a4 != 0.f) | (a5 != 0.f) | (a6 != 0.f) | (a7 != 0.f);
            }
            for (; f < fc; f++)
                rr = rr | (arow[(s_flist[f] << 10) + n] != 0.f);
            s_kmask[n] = (reach1 || rr) ? 1 : 0;
        }
        __syncthreads();

        // ---- grow steps s = 1..15: warp 0 only (R7 version) ----
        if (wid == 0) {
            int cnt = 0;
            for (int base = 0; base < Nn; base += 32) {
                int node = base + lane;
                bool cd = s_avail[node] && s_kmask[node];
                unsigned mk = __ballot_sync(0xffffffffu, cd);
                if (cd) s_clist[cnt + __popc(mk & ((1u << lane) - 1u))] = node;
                cnt += __popc(mk);
            }
            int aliveCnt = cnt;
            int mc = s_mcnt;
            for (int s = 1; s < CSn; s++) {
                if (aliveCnt > 0) {
                    unsigned k0 = SELKEYS.a[c * CSn + s], k1 = SELKEYS.b[c * CSn + s];
                    unsigned long long pk =
                        (((unsigned long long)(~__float_as_uint(NEGV))) << 32);
                    for (int i = lane; i < cnt; i += 32) {
                        int node = s_clist[i];
                        if (node >= 0) {
                            float val = gumbel_val(k0, k1, b, node, s_logit[node]);
                            unsigned long long p2 = packkey(val, node);
                            if (p2 > pk) pk = p2;
                        }
                    }
                    for (int off = 16; off; off >>= 1) {
                        unsigned long long o = __shfl_xor_sync(0xffffffffu, pk, off);
                        if (o > pk) pk = o;
                    }
                    int node = (int)(0xFFFFFFFFu - (unsigned)(pk & 0xFFFFFFFFu));
                    for (int i = lane; i < cnt; i += 32)
                        if (s_clist[i] == node) s_clist[i] = -1;
                    if (lane == 0) {
                        s_avail[node] = 0; s_mem[node] = 1; s_mlist[mc] = node;
                    }
                    mc++;
                    aliveCnt--;
                }
            }
            if (lane == 0) {
                s_mcnt = mc;
                for (int i = 1; i < mc; i++) {
                    int v = s_mlist[i], j = i - 1;
                    while (j >= 0 && s_mlist[j] > v) { s_mlist[j + 1] = s_mlist[j]; j--; }
                    s_mlist[j + 1] = v;
                }
            }
        }
        __syncthreads();

        // ---- cluster embedding (prefetched, order-preserving) ----
        int mc = s_mcnt;
        if (n < Dn) {
            int idxs[CSn];
#pragma unroll
            for (int i = 0; i < CSn; i++) idxs[i] = s_mlist[(i < mc) ? i : 0];
            float e = 0.f;
#pragma unroll
            for (int i = 0; i < CSn; i++) {
                float t = x[((b << 10) + idxs[i]) * Dn + n];
                e += (i < mc) ? t : 0.0f;
            }
            e = e / fmaxf((float)mc, 1.0f);
            s_emb[n] = e;
            out_cf[((b * Sn) + c) * Dn + n] = e;
        }
        out_as[((b << 10) + n) * Sn + c] = s_mem[n] ? 1.0f : 0.0f;
        __syncthreads();

        // ---- GRU: 768 threads; contiguous row-major weight streams ----
        if (n < 768) {
            int p = (n >= 384) ? 1 : 0;
            int j = n - p * 384;
            {
                const float4* w4 = reinterpret_cast<const float4*>(Wih + (j << 8) + p * 128);
                int kb = p * 128;
                float a0 = 0.f, a1 = 0.f, a2 = 0.f, a3 = 0.f,
                      a4 = 0.f, a5 = 0.f, a6 = 0.f, a7 = 0.f;
#pragma unroll 4
                for (int k = 0; k < 128; k += 8) {
                    float4 v0 = w4[k >> 2], v1 = w4[(k >> 2) + 1];
                    a0 = fmaf(s_emb[kb + k + 0], v0.x, a0);
                    a1 = fmaf(s_emb[kb + k + 1], v0.y, a1);
                    a2 = fmaf(s_emb[kb + k + 2], v0.z, a2);
                    a3 = fmaf(s_emb[kb + k + 3], v0.w, a3);
                    a4 = fmaf(s_emb[kb + k + 4], v1.x, a4);
                    a5 = fmaf(s_emb[kb + k + 5], v1.y, a5);
                    a6 = fmaf(s_emb[kb + k + 6], v1.z, a6);
                    a7 = fmaf(s_emb[kb + k + 7], v1.w, a7);
                }
                s_part[p * 384 + j] = ((a0 + a1) + (a2 + a3)) + ((a4 + a5) + (a6 + a7));
            }
            BAR768();
            if (n < 384)
                s_gi[c][n] = bih[n] + s_part[n] + s_part[384 + n];
            BAR768();
            for (int t2 = 0; t2 <= c; t2++) {
                {
                    const float4* w4 = reinterpret_cast<const float4*>(Whh + (j << 7) + p * 64);
                    int kb = p * 64;
                    float a0 = 0.f, a1 = 0.f, a2 = 0.f, a3 = 0.f,
                          a4 = 0.f, a5 = 0.f, a6 = 0.f, a7 = 0.f;
#pragma unroll 2
                    for (int k = 0; k < 64; k += 8) {
                        float4 v0 = w4[k >> 2], v1 = w4[(k >> 2) + 1];
                        a0 = fmaf(s_hidden[kb + k + 0], v0.x, a0);
                        a1 = fmaf(s_hidden[kb + k + 1], v0.y, a1);
                        a2 = fmaf(s_hidden[kb + k + 2], v0.z, a2);
                        a3 = fmaf(s_hidden[kb + k + 3], v0.w, a3);
                        a4 = fmaf(s_hidden[kb + k + 4], v1.x, a4);
                        a5 = fmaf(s_hidden[kb + k + 5], v1.y, a5);
                        a6 = fmaf(s_hidden[kb + k + 6], v1.z, a6);
                        a7 = fmaf(s_hidden[kb + k + 7], v1.w, a7);
                    }
                    s_part[p * 384 + j] = ((a0 + a1) + (a2 + a3)) + ((a4 + a5) + (a6 + a7));
                }
                BAR768();
                if (n < Hn) {
                    float ir = s_gi[t2][n], iz = s_gi[t2][Hn + n], inn = s_gi[t2][2 * Hn + n];
                    float hr = bhh[n] + s_part[n] + s_part[384 + n];
                    float hz = bhh[Hn + n] + s_part[Hn + n] + s_part[384 + Hn + n];
                    float hn = bhh[2 * Hn + n] + s_part[2 * Hn + n] + s_part[384 + 2 * Hn + n];
                    float r = sigm(ir + hr);
                    float z = sigm(iz + hz);
                    float nn = tanhf(inn + r * hn);
                    float hprev = s_hidden[n];
                    s_hidden[n] = (1.0f - z) * nn + z * hprev;
                }
                BAR768();
            }
            if (n < Hn) s_gctx[n] = s_hidden[n];
        }
        __syncthreads();
    }

    // cluster_adj = ones - eye
    if (n < Sn * Sn) {
        int i = n / Sn, j = n % Sn;
        out_ca[b * Sn * Sn + n] = (i == j) ? 0.0f : 1.0f;
    }
}

extern "C" void kernel_launch(void* const* d_in, const int* in_sizes, int n_in,
                              void* d_out, int out_size) {
    (void)in_sizes; (void)out_size;
    int k = (n_in >= 13) ? 3 : 2;
    const float* x   = (const float*)d_in[0];
    const float* adj = (const float*)d_in[1];
    const float* W1  = (const float*)d_in[k + 0];
    const float* b1  = (const float*)d_in[k + 1];
    const float* W2  = (const float*)d_in[k + 2];
    const float* b2  = (const float*)d_in[k + 3];
    const float* Wih = (const float*)d_in[k + 4];
    const float* Whh = (const float*)d_in[k + 5];
    const float* bih = (const float*)d_in[k + 6];
    const float* bhh = (const float*)d_in[k + 7];
    const float* Wc  = (const float*)d_in[k + 8];
    const float* bc  = (const float*)d_in[k + 9];

    k_xw1<<<dim3(16, Bn), 256>>>(x, W1, b1);
    k_xmean<<<dim3(Bn, 8), 256>>>(x);
    k_w1ct<<<(Hn * Hn + 255) / 256, 256>>>(W1);
    k_main<<<Bn, 1024>>>(x, adj, Wih, Whh, W2, b2, bih, bhh, Wc, bc, (float*)d_out);
}

// round 12
// speedup vs baseline: 1.9419x; 1.9419x over previous
#include <cuda_runtime.h>
#include <math.h>
#include <stdint.h>

// Problem constants
#define Bn 16
#define Nn 1024
#define Dn 256
#define Hn 128
#define Sn 12     // MAX_CLUSTERS
#define CSn 16    // CSIZE
#define NEGV (-1e9f)

#define PARTITIONABLE 1

// ---------------- scratch ----------------
__device__ float g_XW1t[Bn * Hn * Nn];      // [b][h][n] = x@W1[:256] + b1
__device__ float g_WihT[Dn * 3 * Hn];       // [256][384]
__device__ float g_WhhT[Hn * 3 * Hn];       // [128][384]
__device__ float g_xpart[Bn][8][Dn];        // partial column sums of x

// ---------------- Threefry2x32 (JAX-exact) ----------------
__device__ __forceinline__ uint2 tf2x32(unsigned k0, unsigned k1, unsigned x0, unsigned x1) {
    unsigned ks2 = k0 ^ k1 ^ 0x1BD11BDAu;
    x0 += k0; x1 += k1;
#define TFR(r) { x0 += x1; x1 = (x1 << (r)) | (x1 >> (32 - (r))); x1 ^= x0; }
    TFR(13) TFR(15) TFR(26) TFR(6)   x0 += k1;  x1 += ks2 + 1u;
    TFR(17) TFR(29) TFR(16) TFR(24)  x0 += ks2; x1 += k0 + 2u;
    TFR(13) TFR(15) TFR(26) TFR(6)   x0 += k0;  x1 += k1 + 3u;
    TFR(17) TFR(29) TFR(16) TFR(24)  x0 += k1;  x1 += ks2 + 4u;
    TFR(13) TFR(15) TFR(26) TFR(6)   x0 += ks2; x1 += k0 + 5u;
#undef TFR
    return make_uint2(x0, x1);
}

struct P2 { unsigned x, y; };
constexpr unsigned rotl_c(unsigned x, int r) { return (x << r) | (x >> (32 - r)); }
constexpr P2 tf_c(unsigned k0, unsigned k1, unsigned x0, unsigned x1) {
    unsigned ks2 = k0 ^ k1 ^ 0x1BD11BDAu;
    x0 += k0; x1 += k1;
    const int R0[4] = {13, 15, 26, 6};
    const int R1[4] = {17, 29, 16, 24};
    for (int i = 0; i < 5; i++) {
        for (int j = 0; j < 4; j++) {
            int r = (i % 2 == 0) ? R0[j] : R1[j];
            x0 += x1; x1 = rotl_c(x1, r); x1 ^= x0;
        }
        int a = (i + 1) % 3, bsel = (i + 2) % 3;
        unsigned inj0 = (a == 0) ? k0 : ((a == 1) ? k1 : ks2);
        unsigned inj1 = (bsel == 0) ? k0 : ((bsel == 1) ? k1 : ks2);
        x0 += inj0; x1 += inj1 + (unsigned)(i + 1);
    }
    return P2{x0, x1};
}

struct KeyTab { unsigned a[Sn * CSn]; unsigned b[Sn * CSn]; };
constexpr KeyTab mk_keys() {
    KeyTab t{};
    unsigned k0 = 0u, k1 = 42u;
    for (int i = 0; i < Sn * CSn; i++) {
#if PARTITIONABLE
        P2 nk = tf_c(k0, k1, 0u, 0u);
        P2 sk = tf_c(k0, k1, 0u, 1u);
        t.a[i] = sk.x; t.b[i] = sk.y;
        k0 = nk.x; k1 = nk.y;
#else
        P2 l0 = tf_c(k0, k1, 0u, 2u);
        P2 l1 = tf_c(k0, k1, 1u, 3u);
        t.a[i] = l0.y; t.b[i] = l1.y;
        k0 = l0.x; k1 = l1.x;
#endif
    }
    return t;
}
static constexpr KeyTab H_KEYS = mk_keys();
__constant__ KeyTab SELKEYS = H_KEYS;

__device__ __forceinline__ unsigned rand_bits(unsigned k0, unsigned k1, unsigned g) {
#if PARTITIONABLE
    uint2 o = tf2x32(k0, k1, 0u, g);
    return o.x ^ o.y;
#else
    const unsigned m = (Bn * Nn) / 2;
    if (g < m) { uint2 o = tf2x32(k0, k1, g, g + m); return o.x; }
    else       { uint2 o = tf2x32(k0, k1, g - m, g); return o.y; }
#endif
}

__device__ __forceinline__ float gumbel_val(unsigned k0, unsigned k1, int b, int node,
                                            float logit) {
    unsigned bits = rand_bits(k0, k1, (unsigned)((b << 10) + node));
    float u = __uint_as_float((bits >> 9) | 0x3f800000u) - 1.0f;
    float s1 = u + 1e-8f;
    float l1 = __logf(s1);
    float s2 = (-l1) + 1e-8f;
    float l2 = __logf(s2);
    return logit + (-l2);
}

__device__ __forceinline__ unsigned long long packkey(float val, int node) {
    unsigned ub = __float_as_uint(val);
    unsigned ord = (ub & 0x80000000u) ? ~ub : (ub | 0x80000000u);
    return (((unsigned long long)ord) << 32) | (unsigned)(0xFFFFFFFFu - node);
}

__device__ __forceinline__ float sigm(float v) {
    return 0.5f * tanhf(0.5f * v) + 0.5f;
}

// ---------------- Kernel 1: tiled SGEMM ----------------
__global__ void __launch_bounds__(256) k_xw1(const float* __restrict__ x,
                                             const float* __restrict__ W1,
                                             const float* __restrict__ b1) {
    __shared__ float xs[64][33];
    __shared__ float ws[32][128];
    int tile = blockIdx.x;
    int b = blockIdx.y;
    int t = threadIdx.x;
    int n0 = tile * 64;
    int nl = t & 63;
    int jbase = (t >> 6) * 32;

    float acc[32];
#pragma unroll
    for (int i = 0; i < 32; i++) acc[i] = 0.f;

    for (int k0 = 0; k0 < Dn; k0 += 32) {
        for (int i = t; i < 64 * 32; i += 256) {
            int nn = i >> 5, kk = i & 31;
            xs[nn][kk] = x[((b << 10) + n0 + nn) * Dn + k0 + kk];
        }
        for (int i = t; i < 32 * 128; i += 256) {
            int kk = i >> 7, jj = i & 127;
            ws[kk][jj] = W1[(k0 + kk) * Hn + jj];
        }
        __syncthreads();
#pragma unroll 4
        for (int k = 0; k < 32; k++) {
            float xv = xs[nl][k];
            const float4* w4 = reinterpret_cast<const float4*>(&ws[k][jbase]);
#pragma unroll
            for (int i = 0; i < 8; i++) {
                float4 w = w4[i];
                acc[4 * i + 0] = fmaf(xv, w.x, acc[4 * i + 0]);
                acc[4 * i + 1] = fmaf(xv, w.y, acc[4 * i + 1]);
                acc[4 * i + 2] = fmaf(xv, w.z, acc[4 * i + 2]);
                acc[4 * i + 3] = fmaf(xv, w.w, acc[4 * i + 3]);
            }
        }
        __syncthreads();
    }
#pragma unroll
    for (int i = 0; i < 32; i++) {
        int j = jbase + i;
        g_XW1t[((b << 7) + j) * Nn + n0 + nl] = acc[i] + b1[j];
    }
}

// ---------------- Kernel 2: transpose GRU weights ----------------
__global__ void k_transpose(const float* __restrict__ Wih, const float* __restrict__ Whh) {
    int idx = blockIdx.x * blockDim.x + threadIdx.x;
    if (idx < 384 * 256) { int j = idx / 256, k = idx % 256; g_WihT[k * 384 + j] = Wih[idx]; }
    if (idx < 384 * 128) { int j = idx / 128, k = idx % 128; g_WhhT[k * 384 + j] = Whh[idx]; }
}

// ---------------- Kernel 3: xmean partials (deterministic) ----------------
__global__ void __launch_bounds__(256) k_xmean(const float* __restrict__ x) {
    int b = blockIdx.x, p = blockIdx.y;   // 16 x 8
    int t = threadIdx.x;                  // column 0..255
    const float* px = x + (((long)(b) << 10) + p * 128) * Dn + t;
    float a0 = 0.f, a1 = 0.f, a2 = 0.f, a3 = 0.f, a4 = 0.f, a5 = 0.f, a6 = 0.f, a7 = 0.f;
    for (int m = 0; m < 128; m += 8) {
        a0 += px[(m + 0) * Dn]; a1 += px[(m + 1) * Dn];
        a2 += px[(m + 2) * Dn]; a3 += px[(m + 3) * Dn];
        a4 += px[(m + 4) * Dn]; a5 += px[(m + 5) * Dn];
        a6 += px[(m + 6) * Dn]; a7 += px[(m + 7) * Dn];
    }
    g_xpart[b][p][t] = ((a0 + a1) + (a2 + a3)) + ((a4 + a5) + (a6 + a7));
}

#define BAR768() asm volatile("bar.sync 1, 768;" ::: "memory")

// ---------------- Main kernel (R7 structure + emb prefetch + __logf) ----------------
__global__ void __launch_bounds__(1024) k_main(
    const float* __restrict__ x, const float* __restrict__ adj,
    const float* __restrict__ W1, const float* __restrict__ W2, const float* __restrict__ b2,
    const float* __restrict__ bih, const float* __restrict__ bhh,
    const float* __restrict__ Wc, const float* __restrict__ bc,
    float* __restrict__ out) {
    int b = blockIdx.x;
    int n = threadIdx.x;
    int lane = n & 31, wid = n >> 5;

    __shared__ float s_logit[Nn];
    __shared__ float s_ctx[Hn], s_gctx[Hn], s_hidden[Hn];
    __shared__ float s_part[768];
    __shared__ float s_gi[Sn][3 * Hn];
    __shared__ float s_emb[Dn];
    __shared__ float s_w2[Hn];
    __shared__ unsigned char s_avail[Nn], s_mem[Nn], s_kmask[Nn];
    __shared__ int s_clist[Nn];
    __shared__ int s_flist[Nn];
    __shared__ int s_fcnt;
    __shared__ unsigned long long s_red[32];
    __shared__ int s_mlist[CSn + 1];
    __shared__ int s_mcnt;

    s_avail[n] = 1;
    if (n < Dn) {
        float s = ((g_xpart[b][0][n] + g_xpart[b][1][n]) + (g_xpart[b][2][n] + g_xpart[b][3][n]))
                + ((g_xpart[b][4][n] + g_xpart[b][5][n]) + (g_xpart[b][6][n] + g_xpart[b][7][n]));
        s_emb[n] = s / 1024.0f;
    }
    if (n < Hn) s_w2[n] = W2[n];
    __syncthreads();
    if (n < Hn) {
        float a0 = 0.f, a1 = 0.f, a2 = 0.f, a3 = 0.f;
        for (int d = 0; d < Dn; d += 4) {
            a0 = fmaf(s_emb[d + 0], Wc[(d + 0) * Hn + n], a0);
            a1 = fmaf(s_emb[d + 1], Wc[(d + 1) * Hn + n], a1);
            a2 = fmaf(s_emb[d + 2], Wc[(d + 2) * Hn + n], a2);
            a3 = fmaf(s_emb[d + 3], Wc[(d + 3) * Hn + n], a3);
        }
        s_gctx[n] = bc[n] + ((a0 + a1) + (a2 + a3));
        s_hidden[n] = 0.f;
    }
    float b2v = b2[0];
    __syncthreads();

    float* out_cf = out;                       // [16][12][256]
    float* out_ca = out + Bn * Sn * Dn;        // [16][12][12]
    float* out_as = out_ca + Bn * Sn * Sn;     // [16][1024][12]

    const float* arow = adj + ((long)b << 20);

    for (int c = 0; c < Sn; c++) {
        s_mem[n] = 0;
        if (n == 0) s_fcnt = 0;
        // ctx partials: 512 threads, 4 parts x 32 k
        if (n < 512) {
            int p = n >> 7, j = n & 127;
            int kb = Dn + p * 32;
            float a0 = 0.f, a1 = 0.f, a2 = 0.f, a3 = 0.f;
#pragma unroll
            for (int k = 0; k < 32; k += 4) {
                a0 = fmaf(s_gctx[p * 32 + k + 0], W1[(kb + k + 0) * Hn + j], a0);
                a1 = fmaf(s_gctx[p * 32 + k + 1], W1[(kb + k + 1) * Hn + j], a1);
                a2 = fmaf(s_gctx[p * 32 + k + 2], W1[(kb + k + 2) * Hn + j], a2);
                a3 = fmaf(s_gctx[p * 32 + k + 3], W1[(kb + k + 3) * Hn + j], a3);
            }
            s_part[p * 128 + j] = (a0 + a1) + (a2 + a3);
        }
        __syncthreads();
        if (n < Hn)
            s_ctx[n] = (s_part[n] + s_part[128 + n]) + (s_part[256 + n] + s_part[384 + n]);
        __syncthreads();

        // logits
        float mylogit;
        {
            float acc = 0.f;
            const float* px = g_XW1t + ((long)(b) << 7) * Nn + n;
#pragma unroll 8
            for (int j = 0; j < Hn; j++) {
                float v = px[j * Nn] + s_ctx[j];
                acc = fmaf(fmaxf(v, 0.f), s_w2[j], acc);
            }
            mylogit = acc + b2v;
            s_logit[n] = mylogit;
        }

        // seed selection
        {
            unsigned k0 = SELKEYS.a[c * CSn + 0], k1 = SELKEYS.b[c * CSn + 0];
            float val = NEGV;
            if (s_avail[n]) val = gumbel_val(k0, k1, b, n, mylogit);
            unsigned long long pk = packkey(val, n);
            for (int off = 16; off; off >>= 1) {
                unsigned long long o = __shfl_down_sync(0xffffffffu, pk, off);
                if (o > pk) pk = o;
            }
            if (lane == 0) s_red[wid] = pk;
        }
        __syncthreads();
        int sel, valid;
        {
            unsigned long long v2 = s_red[lane];
            for (int off = 16; off; off >>= 1) {
                unsigned long long o = __shfl_down_sync(0xffffffffu, v2, off);
                if (o > v2) v2 = o;
            }
            v2 = __shfl_sync(0xffffffffu, v2, 0);
            sel = (int)(0xFFFFFFFFu - (unsigned)(v2 & 0xFFFFFFFFu));
            unsigned ordv = (unsigned)(v2 >> 32);
            unsigned fb = (ordv & 0x80000000u) ? (ordv ^ 0x80000000u) : ~ordv;
            valid = (__uint_as_float(fb) > -1e8f) ? 1 : 0;
        }
        if (valid && n == sel) { s_avail[n] = 0; s_mem[n] = 1; }
        if (n == 0) {
            s_mcnt = valid ? 1 : 0;
            if (valid) s_mlist[0] = sel;
        }

        // ---- 2-hop BFS ----
        bool nb1 = (arow[(sel << 10) + n] != 0.0f);
        bool reach1 = (n == sel) || nb1;
        if (nb1 && n != sel) { int p = atomicAdd(&s_fcnt, 1); s_flist[p] = n; }
        __syncthreads();
        {
            int fc = s_fcnt;
            bool rr = false;
            int f = 0;
            for (; f + 8 <= fc; f += 8) {
                float a0 = arow[(s_flist[f + 0] << 10) + n];
                float a1 = arow[(s_flist[f + 1] << 10) + n];
                float a2 = arow[(s_flist[f + 2] << 10) + n];
                float a3 = arow[(s_flist[f + 3] << 10) + n];
                float a4 = arow[(s_flist[f + 4] << 10) + n];
                float a5 = arow[(s_flist[f + 5] << 10) + n];
                float a6 = arow[(s_flist[f + 6] << 10) + n];
                float a7 = arow[(s_flist[f + 7] << 10) + n];
                rr = rr | (a0 != 0.f) | (a1 != 0.f) | (a2 != 0.f) | (a3 != 0.f)
                        | (a4 != 0.f) | (a5 != 0.f) | (a6 != 0.f) | (a7 != 0.f);
            }
            for (; f < fc; f++)
                rr = rr | (arow[(s_flist[f] << 10) + n] != 0.f);
            s_kmask[n] = (reach1 || rr) ? 1 : 0;
        }
        __syncthreads();

        // ---- grow steps s = 1..15: warp 0 only ----
        if (wid == 0) {
            int cnt = 0;
            for (int base = 0; base < Nn; base += 32) {
                int node = base + lane;
                bool cd = s_avail[node] && s_kmask[node];
                unsigned mk = __ballot_sync(0xffffffffu, cd);
                if (cd) s_clist[cnt + __popc(mk & ((1u << lane) - 1u))] = node;
                cnt += __popc(mk);
            }
            int aliveCnt = cnt;
            int mc = s_mcnt;
            for (int s = 1; s < CSn; s++) {
                if (aliveCnt > 0) {
                    unsigned k0 = SELKEYS.a[c * CSn + s], k1 = SELKEYS.b[c * CSn + s];
                    unsigned long long pk =
                        (((unsigned long long)(~__float_as_uint(NEGV))) << 32);
                    for (int i = lane; i < cnt; i += 32) {
                        int node = s_clist[i];
                        if (node >= 0) {
                            float val = gumbel_val(k0, k1, b, node, s_logit[node]);
                            unsigned long long p2 = packkey(val, node);
                            if (p2 > pk) pk = p2;
                        }
                    }
                    for (int off = 16; off; off >>= 1) {
                        unsigned long long o = __shfl_xor_sync(0xffffffffu, pk, off);
                        if (o > pk) pk = o;
                    }
                    int node = (int)(0xFFFFFFFFu - (unsigned)(pk & 0xFFFFFFFFu));
                    for (int i = lane; i < cnt; i += 32)
                        if (s_clist[i] == node) s_clist[i] = -1;
                    if (lane == 0) {
                        s_avail[node] = 0; s_mem[node] = 1; s_mlist[mc] = node;
                    }
                    mc++;
                    aliveCnt--;
                }
            }
            if (lane == 0) {
                s_mcnt = mc;
                for (int i = 1; i < mc; i++) {
                    int v = s_mlist[i], j = i - 1;
                    while (j >= 0 && s_mlist[j] > v) { s_mlist[j + 1] = s_mlist[j]; j--; }
                    s_mlist[j + 1] = v;
                }
            }
        }
        __syncthreads();

        // ---- cluster embedding (prefetched parallel loads, order-preserving sum) ----
        int mc = s_mcnt;
        if (n < Dn) {
            int idxs[CSn];
#pragma unroll
            for (int i = 0; i < CSn; i++) idxs[i] = s_mlist[(i < mc) ? i : 0];
            float e = 0.f;
#pragma unroll
            for (int i = 0; i < CSn; i++) {
                float t = x[((b << 10) + idxs[i]) * Dn + n];
                e += (i < mc) ? t : 0.0f;
            }
            e = e / fmaxf((float)mc, 1.0f);
            s_emb[n] = e;
            out_cf[((b * Sn) + c) * Dn + n] = e;
        }
        out_as[((b << 10) + n) * Sn + c] = s_mem[n] ? 1.0f : 0.0f;
        __syncthreads();

        // ---- GRU: 768 threads; partials in s_part (coalesced transposed weights) ----
        if (n < 768) {
            int p = (n >= 384) ? 1 : 0;
            int j = n - p * 384;
            {
                const float* w = g_WihT + j;
                int kb = p * 128;
                float a0 = 0.f, a1 = 0.f, a2 = 0.f, a3 = 0.f,
                      a4 = 0.f, a5 = 0.f, a6 = 0.f, a7 = 0.f;
#pragma unroll 4
                for (int k = 0; k < 128; k += 8) {
                    a0 = fmaf(s_emb[kb + k + 0], w[(kb + k + 0) * 384], a0);
                    a1 = fmaf(s_emb[kb + k + 1], w[(kb + k + 1) * 384], a1);
                    a2 = fmaf(s_emb[kb + k + 2], w[(kb + k + 2) * 384], a2);
                    a3 = fmaf(s_emb[kb + k + 3], w[(kb + k + 3) * 384], a3);
                    a4 = fmaf(s_emb[kb + k + 4], w[(kb + k + 4) * 384], a4);
                    a5 = fmaf(s_emb[kb + k + 5], w[(kb + k + 5) * 384], a5);
                    a6 = fmaf(s_emb[kb + k + 6], w[(kb + k + 6) * 384], a6);
                    a7 = fmaf(s_emb[kb + k + 7], w[(kb + k + 7) * 384], a7);
                }
                s_part[p * 384 + j] = ((a0 + a1) + (a2 + a3)) + ((a4 + a5) + (a6 + a7));
            }
            BAR768();
            if (n < 384)
                s_gi[c][n] = bih[n] + s_part[n] + s_part[384 + n];
            BAR768();
            for (int t2 = 0; t2 <= c; t2++) {
                {
                    const float* w = g_WhhT + j;
                    int kb = p * 64;
                    float a0 = 0.f, a1 = 0.f, a2 = 0.f, a3 = 0.f,
                          a4 = 0.f, a5 = 0.f, a6 = 0.f, a7 = 0.f;
#pragma unroll 2
                    for (int k = 0; k < 64; k += 8) {
                        a0 = fmaf(s_hidden[kb + k + 0], w[(kb + k + 0) * 384], a0);
                        a1 = fmaf(s_hidden[kb + k + 1], w[(kb + k + 1) * 384], a1);
                        a2 = fmaf(s_hidden[kb + k + 2], w[(kb + k + 2) * 384], a2);
                        a3 = fmaf(s_hidden[kb + k + 3], w[(kb + k + 3) * 384], a3);
                        a4 = fmaf(s_hidden[kb + k + 4], w[(kb + k + 4) * 384], a4);
                        a5 = fmaf(s_hidden[kb + k + 5], w[(kb + k + 5) * 384], a5);
                        a6 = fmaf(s_hidden[kb + k + 6], w[(kb + k + 6) * 384], a6);
                        a7 = fmaf(s_hidden[kb + k + 7], w[(kb + k + 7) * 384], a7);
                    }
                    s_part[p * 384 + j] = ((a0 + a1) + (a2 + a3)) + ((a4 + a5) + (a6 + a7));
                }
                BAR768();
                if (n < Hn) {
                    float ir = s_gi[t2][n], iz = s_gi[t2][Hn + n], inn = s_gi[t2][2 * Hn + n];
                    float hr = bhh[n] + s_part[n] + s_part[384 + n];
                    float hz = bhh[Hn + n] + s_part[Hn + n] + s_part[384 + Hn + n];
                    float hn = bhh[2 * Hn + n] + s_part[2 * Hn + n] + s_part[384 + 2 * Hn + n];
                    float r = sigm(ir + hr);
                    float z = sigm(iz + hz);
                    float nn = tanhf(inn + r * hn);
                    float hprev = s_hidden[n];
                    s_hidden[n] = (1.0f - z) * nn + z * hprev;
                }
                BAR768();
            }
            if (n < Hn) s_gctx[n] = s_hidden[n];
        }
        __syncthreads();
    }

    // cluster_adj = ones - eye
    if (n < Sn * Sn) {
        int i = n / Sn, j = n % Sn;
        out_ca[b * Sn * Sn + n] = (i == j) ? 0.0f : 1.0f;
    }
}

extern "C" void kernel_launch(void* const* d_in, const int* in_sizes, int n_in,
                              void* d_out, int out_size) {
    (void)in_sizes; (void)out_size;
    int k = (n_in >= 13) ? 3 : 2;
    const float* x   = (const float*)d_in[0];
    const float* adj = (const float*)d_in[1];
    const float* W1  = (const float*)d_in[k + 0];
    const float* b1  = (const float*)d_in[k + 1];
    const float* W2  = (const float*)d_in[k + 2];
    const float* b2  = (const float*)d_in[k + 3];
    const float* Wih = (const float*)d_in[k + 4];
    const float* Whh = (const float*)d_in[k + 5];
    const float* bih = (const float*)d_in[k + 6];
    const float* bhh = (const float*)d_in[k + 7];
    const float* Wc  = (const float*)d_in[k + 8];
    const float* bc  = (const float*)d_in[k + 9];

    k_xw1<<<dim3(16, Bn), 256>>>(x, W1, b1);
    k_xmean<<<dim3(Bn, 8), 256>>>(x);
    k_transpose<<<(384 * 256 + 255) / 256, 256>>>(Wih, Whh);
    k_main<<<Bn, 1024>>>(x, adj, W1, W2, b2, bih, bhh, Wc, bc, (float*)d_out);
}

// round 15
// speedup vs baseline: 2.3092x; 1.1891x over previous
#include <cuda_runtime.h>
#include <math.h>
#include <stdint.h>

// Problem constants
#define Bn 16
#define Nn 1024
#define Dn 256
#define Hn 128
#define Sn 12     // MAX_CLUSTERS
#define CSn 16    // CSIZE
#define NEGV (-1e9f)

#define PARTITIONABLE 1

// ---------------- scratch ----------------
__device__ float g_XW1t[Bn * Hn * Nn];      // [b][h][n] = x@W1[:256] + b1
__device__ float g_WihT[Dn * 3 * Hn];       // [256][384]
__device__ float g_WhhT[Hn * 3 * Hn];       // [128][384]
__device__ float g_xpart[Bn][8][Dn];        // partial column sums of x
__device__ float g_gi[Bn * Sn * 3 * Hn];    // per-cluster input gates

// ---------------- Threefry2x32 (JAX-exact) ----------------
__device__ __forceinline__ uint2 tf2x32(unsigned k0, unsigned k1, unsigned x0, unsigned x1) {
    unsigned ks2 = k0 ^ k1 ^ 0x1BD11BDAu;
    x0 += k0; x1 += k1;
#define TFR(r) { x0 += x1; x1 = (x1 << (r)) | (x1 >> (32 - (r))); x1 ^= x0; }
    TFR(13) TFR(15) TFR(26) TFR(6)   x0 += k1;  x1 += ks2 + 1u;
    TFR(17) TFR(29) TFR(16) TFR(24)  x0 += ks2; x1 += k0 + 2u;
    TFR(13) TFR(15) TFR(26) TFR(6)   x0 += k0;  x1 += k1 + 3u;
    TFR(17) TFR(29) TFR(16) TFR(24)  x0 += k1;  x1 += ks2 + 4u;
    TFR(13) TFR(15) TFR(26) TFR(6)   x0 += ks2; x1 += k0 + 5u;
#undef TFR
    return make_uint2(x0, x1);
}

struct P2 { unsigned x, y; };
constexpr unsigned rotl_c(unsigned x, int r) { return (x << r) | (x >> (32 - r)); }
constexpr P2 tf_c(unsigned k0, unsigned k1, unsigned x0, unsigned x1) {
    unsigned ks2 = k0 ^ k1 ^ 0x1BD11BDAu;
    x0 += k0; x1 += k1;
    const int R0[4] = {13, 15, 26, 6};
    const int R1[4] = {17, 29, 16, 24};
    for (int i = 0; i < 5; i++) {
        for (int j = 0; j < 4; j++) {
            int r = (i % 2 == 0) ? R0[j] : R1[j];
            x0 += x1; x1 = rotl_c(x1, r); x1 ^= x0;
        }
        int a = (i + 1) % 3, bsel = (i + 2) % 3;
        unsigned inj0 = (a == 0) ? k0 : ((a == 1) ? k1 : ks2);
        unsigned inj1 = (bsel == 0) ? k0 : ((bsel == 1) ? k1 : ks2);
        x0 += inj0; x1 += inj1 + (unsigned)(i + 1);
    }
    return P2{x0, x1};
}

struct KeyTab { unsigned a[Sn * CSn]; unsigned b[Sn * CSn]; };
constexpr KeyTab mk_keys() {
    KeyTab t{};
    unsigned k0 = 0u, k1 = 42u;
    for (int i = 0; i < Sn * CSn; i++) {
#if PARTITIONABLE
        P2 nk = tf_c(k0, k1, 0u, 0u);
        P2 sk = tf_c(k0, k1, 0u, 1u);
        t.a[i] = sk.x; t.b[i] = sk.y;
        k0 = nk.x; k1 = nk.y;
#else
        P2 l0 = tf_c(k0, k1, 0u, 2u);
        P2 l1 = tf_c(k0, k1, 1u, 3u);
        t.a[i] = l0.y; t.b[i] = l1.y;
        k0 = l0.x; k1 = l1.x;
#endif
    }
    return t;
}
static constexpr KeyTab H_KEYS = mk_keys();
__constant__ KeyTab SELKEYS = H_KEYS;

__device__ __forceinline__ unsigned rand_bits(unsigned k0, unsigned k1, unsigned g) {
#if PARTITIONABLE
    uint2 o = tf2x32(k0, k1, 0u, g);
    return o.x ^ o.y;
#else
    const unsigned m = (Bn * Nn) / 2;
    if (g < m) { uint2 o = tf2x32(k0, k1, g, g + m); return o.x; }
    else       { uint2 o = tf2x32(k0, k1, g - m, g); return o.y; }
#endif
}

__device__ __forceinline__ float gumbel_val(unsigned k0, unsigned k1, int b, int node,
                                            float logit) {
    unsigned bits = rand_bits(k0, k1, (unsigned)((b << 10) + node));
    float u = __uint_as_float((bits >> 9) | 0x3f800000u) - 1.0f;
    float s1 = u + 1e-8f;
    float l1 = logf(s1);
    float s2 = (-l1) + 1e-8f;
    float l2 = logf(s2);
    return logit + (-l2);
}

__device__ __forceinline__ unsigned long long packkey(float val, int node) {
    unsigned ub = __float_as_uint(val);
    unsigned ord = (ub & 0x80000000u) ? ~ub : (ub | 0x80000000u);
    return (((unsigned long long)ord) << 32) | (unsigned)(0xFFFFFFFFu - node);
}

__device__ __forceinline__ float sigm(float v) {
    return 0.5f * tanhf(0.5f * v) + 0.5f;
}

// ---------------- Kernel 1: tiled SGEMM ----------------
__global__ void __launch_bounds__(256) k_xw1(const float* __restrict__ x,
                                             const float* __restrict__ W1,
                                             const float* __restrict__ b1) {
    __shared__ float xs[64][33];
    __shared__ float ws[32][128];
    int tile = blockIdx.x;
    int b = blockIdx.y;
    int t = threadIdx.x;
    int n0 = tile * 64;
    int nl = t & 63;
    int jbase = (t >> 6) * 32;

    float acc[32];
#pragma unroll
    for (int i = 0; i < 32; i++) acc[i] = 0.f;

    for (int k0 = 0; k0 < Dn; k0 += 32) {
        for (int i = t; i < 64 * 32; i += 256) {
            int nn = i >> 5, kk = i & 31;
            xs[nn][kk] = x[((b << 10) + n0 + nn) * Dn + k0 + kk];
        }
        for (int i = t; i < 32 * 128; i += 256) {
            int kk = i >> 7, jj = i & 127;
            ws[kk][jj] = W1[(k0 + kk) * Hn + jj];
        }
        __syncthreads();
#pragma unroll 4
        for (int k = 0; k < 32; k++) {
            float xv = xs[nl][k];
            const float4* w4 = reinterpret_cast<const float4*>(&ws[k][jbase]);
#pragma unroll
            for (int i = 0; i < 8; i++) {
                float4 w = w4[i];
                acc[4 * i + 0] = fmaf(xv, w.x, acc[4 * i + 0]);
                acc[4 * i + 1] = fmaf(xv, w.y, acc[4 * i + 1]);
                acc[4 * i + 2] = fmaf(xv, w.z, acc[4 * i + 2]);
                acc[4 * i + 3] = fmaf(xv, w.w, acc[4 * i + 3]);
            }
        }
        __syncthreads();
    }
#pragma unroll
    for (int i = 0; i < 32; i++) {
        int j = jbase + i;
        g_XW1t[((b << 7) + j) * Nn + n0 + nl] = acc[i] + b1[j];
    }
}

// ---------------- Kernel 2: transpose GRU weights ----------------
__global__ void k_transpose(const float* __restrict__ Wih, const float* __restrict__ Whh) {
    int idx = blockIdx.x * blockDim.x + threadIdx.x;
    if (idx < 384 * 256) { int j = idx / 256, k = idx % 256; g_WihT[k * 384 + j] = Wih[idx]; }
    if (idx < 384 * 128) { int j = idx / 128, k = idx % 128; g_WhhT[k * 384 + j] = Whh[idx]; }
}

// ---------------- Kernel 3: xmean partials (deterministic) ----------------
__global__ void __launch_bounds__(256) k_xmean(const float* __restrict__ x) {
    int b = blockIdx.x, p = blockIdx.y;   // 16 x 8
    int t = threadIdx.x;                  // column 0..255
    const float* px = x + (((long)(b) << 10) + p * 128) * Dn + t;
    float a0 = 0.f, a1 = 0.f, a2 = 0.f, a3 = 0.f, a4 = 0.f, a5 = 0.f, a6 = 0.f, a7 = 0.f;
    for (int m = 0; m < 128; m += 8) {
        a0 += px[(m + 0) * Dn]; a1 += px[(m + 1) * Dn];
        a2 += px[(m + 2) * Dn]; a3 += px[(m + 3) * Dn];
        a4 += px[(m + 4) * Dn]; a5 += px[(m + 5) * Dn];
        a6 += px[(m + 6) * Dn]; a7 += px[(m + 7) * Dn];
    }
    g_xpart[b][p][t] = ((a0 + a1) + (a2 + a3)) + ((a4 + a5) + (a6 + a7));
}

#define BAR768() asm volatile("bar.sync 1, 768;" ::: "memory")

#define WHH_F (Hn * 3 * Hn)   // 49152 floats
// dynamic smem bytes: whh + block state
#define SMEM_BYTES (218448)

// ---------------- Main kernel (R7 + WhhT in smem, gi in global) ----------------
__global__ void __launch_bounds__(1024) k_main(
    const float* __restrict__ x, const float* __restrict__ adj,
    const float* __restrict__ W1, const float* __restrict__ W2, const float* __restrict__ b2,
    const float* __restrict__ bih, const float* __restrict__ bhh,
    const float* __restrict__ Wc, const float* __restrict__ bc,
    float* __restrict__ out) {
    int b = blockIdx.x;
    int n = threadIdx.x;
    int lane = n & 31, wid = n >> 5;

    extern __shared__ float dsm[];
    float* s_whh   = dsm;                    // 49152
    float* s_logit = dsm + WHH_F;            // 1024
    float* s_ctx   = s_logit + Nn;           // 128
    float* s_gctx  = s_ctx + Hn;             // 128
    float* s_hidden= s_gctx + Hn;            // 128
    float* s_part  = s_hidden + Hn;          // 768
    float* s_emb   = s_part + 768;           // 256
    float* s_w2    = s_emb + Dn;             // 128
    unsigned char* s_avail = (unsigned char*)(s_w2 + Hn);
    unsigned char* s_mem   = s_avail + Nn;
    unsigned char* s_kmask = s_mem + Nn;
    int* s_clist = (int*)(s_kmask + Nn);
    int* s_flist = s_clist + Nn;
    unsigned long long* s_red = (unsigned long long*)(s_flist + Nn);
    int* s_mlist = (int*)(s_red + 32);
    int* s_fcnt = s_mlist + CSn + 1;
    int* s_mcnt = s_fcnt + 1;

    // load WhhT into smem (coalesced; one-time)
    for (int i = n; i < WHH_F; i += 1024) s_whh[i] = g_WhhT[i];

    s_avail[n] = 1;
    if (n < Dn) {
        float s = ((g_xpart[b][0][n] + g_xpart[b][1][n]) + (g_xpart[b][2][n] + g_xpart[b][3][n]))
                + ((g_xpart[b][4][n] + g_xpart[b][5][n]) + (g_xpart[b][6][n] + g_xpart[b][7][n]));
        s_emb[n] = s / 1024.0f;
    }
    if (n < Hn) s_w2[n] = W2[n];
    __syncthreads();
    if (n < Hn) {
        float a0 = 0.f, a1 = 0.f, a2 = 0.f, a3 = 0.f;
        for (int d = 0; d < Dn; d += 4) {
            a0 = fmaf(s_emb[d + 0], Wc[(d + 0) * Hn + n], a0);
            a1 = fmaf(s_emb[d + 1], Wc[(d + 1) * Hn + n], a1);
            a2 = fmaf(s_emb[d + 2], Wc[(d + 2) * Hn + n], a2);
            a3 = fmaf(s_emb[d + 3], Wc[(d + 3) * Hn + n], a3);
        }
        s_gctx[n] = bc[n] + ((a0 + a1) + (a2 + a3));
        s_hidden[n] = 0.f;
    }
    float b2v = b2[0];
    // bhh cached in registers for the cell update (values identical)
    float bh0 = 0.f, bh1 = 0.f, bh2 = 0.f;
    if (n < Hn) { bh0 = bhh[n]; bh1 = bhh[Hn + n]; bh2 = bhh[2 * Hn + n]; }
    __syncthreads();

    float* out_cf = out;                       // [16][12][256]
    float* out_ca = out + Bn * Sn * Dn;        // [16][12][12]
    float* out_as = out_ca + Bn * Sn * Sn;     // [16][1024][12]

    const float* arow = adj + ((long)b << 20);

    for (int c = 0; c < Sn; c++) {
        s_mem[n] = 0;
        if (n == 0) *s_fcnt = 0;
        // ctx partials: 512 threads, 4 parts x 32 k
        if (n < 512) {
            int p = n >> 7, j = n & 127;
            int kb = Dn + p * 32;
            float a0 = 0.f, a1 = 0.f, a2 = 0.f, a3 = 0.f;
#pragma unroll
            for (int k = 0; k < 32; k += 4) {
                a0 = fmaf(s_gctx[p * 32 + k + 0], W1[(kb + k + 0) * Hn + j], a0);
                a1 = fmaf(s_gctx[p * 32 + k + 1], W1[(kb + k + 1) * Hn + j], a1);
                a2 = fmaf(s_gctx[p * 32 + k + 2], W1[(kb + k + 2) * Hn + j], a2);
                a3 = fmaf(s_gctx[p * 32 + k + 3], W1[(kb + k + 3) * Hn + j], a3);
            }
            s_part[p * 128 + j] = (a0 + a1) + (a2 + a3);
        }
        __syncthreads();
        if (n < Hn)
            s_ctx[n] = (s_part[n] + s_part[128 + n]) + (s_part[256 + n] + s_part[384 + n]);
        __syncthreads();

        // logits
        float mylogit;
        {
            float acc = 0.f;
            const float* px = g_XW1t + ((long)(b) << 7) * Nn + n;
#pragma unroll 8
            for (int j = 0; j < Hn; j++) {
                float v = px[j * Nn] + s_ctx[j];
                acc = fmaf(fmaxf(v, 0.f), s_w2[j], acc);
            }
            mylogit = acc + b2v;
            s_logit[n] = mylogit;
        }

        // seed selection
        {
            unsigned k0 = SELKEYS.a[c * CSn + 0], k1 = SELKEYS.b[c * CSn + 0];
            float val = NEGV;
            if (s_avail[n]) val = gumbel_val(k0, k1, b, n, mylogit);
            unsigned long long pk = packkey(val, n);
            for (int off = 16; off; off >>= 1) {
                unsigned long long o = __shfl_down_sync(0xffffffffu, pk, off);
                if (o > pk) pk = o;
            }
            if (lane == 0) s_red[wid] = pk;
        }
        __syncthreads();
        int sel, valid;
        {
            unsigned long long v2 = s_red[lane];
            for (int off = 16; off; off >>= 1) {
                unsigned long long o = __shfl_down_sync(0xffffffffu, v2, off);
                if (o > v2) v2 = o;
            }
            v2 = __shfl_sync(0xffffffffu, v2, 0);
            sel = (int)(0xFFFFFFFFu - (unsigned)(v2 & 0xFFFFFFFFu));
            unsigned ordv = (unsigned)(v2 >> 32);
            unsigned fb = (ordv & 0x80000000u) ? (ordv ^ 0x80000000u) : ~ordv;
            valid = (__uint_as_float(fb) > -1e8f) ? 1 : 0;
        }
        if (valid && n == sel) { s_avail[n] = 0; s_mem[n] = 1; }
        if (n == 0) {
            *s_mcnt = valid ? 1 : 0;
            if (valid) s_mlist[0] = sel;
        }

        // ---- 2-hop BFS ----
        bool nb1 = (arow[(sel << 10) + n] != 0.0f);
        bool reach1 = (n == sel) || nb1;
        if (nb1 && n != sel) { int p = atomicAdd(s_fcnt, 1); s_flist[p] = n; }
        __syncthreads();
        {
            int fc = *s_fcnt;
            bool rr = false;
            int f = 0;
            for (; f + 8 <= fc; f += 8) {
                float a0 = arow[(s_flist[f + 0] << 10) + n];
                float a1 = arow[(s_flist[f + 1] << 10) + n];
                float a2 = arow[(s_flist[f + 2] << 10) + n];
                float a3 = arow[(s_flist[f + 3] << 10) + n];
                float a4 = arow[(s_flist[f + 4] << 10) + n];
                float a5 = arow[(s_flist[f + 5] << 10) + n];
                float a6 = arow[(s_flist[f + 6] << 10) + n];
                float a7 = arow[(s_flist[f + 7] << 10) + n];
                rr = rr | (a0 != 0.f) | (a1 != 0.f) | (a2 != 0.f) | (a3 != 0.f)
                        | (a4 != 0.f) | (a5 != 0.f) | (a6 != 0.f) | (a7 != 0.f);
            }
            for (; f < fc; f++)
                rr = rr | (arow[(s_flist[f] << 10) + n] != 0.f);
            s_kmask[n] = (reach1 || rr) ? 1 : 0;
        }
        __syncthreads();

        // ---- grow steps s = 1..15: warp 0 only ----
        if (wid == 0) {
            int cnt = 0;
            for (int base = 0; base < Nn; base += 32) {
                int node = base + lane;
                bool cd = s_avail[node] && s_kmask[node];
                unsigned mk = __ballot_sync(0xffffffffu, cd);
                if (cd) s_clist[cnt + __popc(mk & ((1u << lane) - 1u))] = node;
                cnt += __popc(mk);
            }
            int aliveCnt = cnt;
            int mc = *s_mcnt;
            for (int s = 1; s < CSn; s++) {
                if (aliveCnt > 0) {
                    unsigned k0 = SELKEYS.a[c * CSn + s], k1 = SELKEYS.b[c * CSn + s];
                    unsigned long long pk =
                        (((unsigned long long)(~__float_as_uint(NEGV))) << 32);
                    for (int i = lane; i < cnt; i += 32) {
                        int node = s_clist[i];
                        if (node >= 0) {
                            float val = gumbel_val(k0, k1, b, node, s_logit[node]);
                            unsigned long long p2 = packkey(val, node);
                            if (p2 > pk) pk = p2;
                        }
                    }
                    for (int off = 16; off; off >>= 1) {
                        unsigned long long o = __shfl_xor_sync(0xffffffffu, pk, off);
                        if (o > pk) pk = o;
                    }
                    int node = (int)(0xFFFFFFFFu - (unsigned)(pk & 0xFFFFFFFFu));
                    for (int i = lane; i < cnt; i += 32)
                        if (s_clist[i] == node) s_clist[i] = -1;
                    if (lane == 0) {
                        s_avail[node] = 0; s_mem[node] = 1; s_mlist[mc] = node;
                    }
                    mc++;
                    aliveCnt--;
                }
            }
            if (lane == 0) {
                *s_mcnt = mc;
                for (int i = 1; i < mc; i++) {
                    int v = s_mlist[i], j = i - 1;
                    while (j >= 0 && s_mlist[j] > v) { s_mlist[j + 1] = s_mlist[j]; j--; }
                    s_mlist[j + 1] = v;
                }
            }
        }
        __syncthreads();

        // ---- cluster embedding (R7 serial order-preserving sum) ----
        int mc = *s_mcnt;
        if (n < Dn) {
            float e = 0.f;
            for (int i = 0; i < mc; i++) e += x[((b << 10) + s_mlist[i]) * Dn + n];
            e = e / fmaxf((float)mc, 1.0f);
            s_emb[n] = e;
            out_cf[((b * Sn) + c) * Dn + n] = e;
        }
        out_as[((b << 10) + n) * Sn + c] = s_mem[n] ? 1.0f : 0.0f;
        __syncthreads();

        // ---- GRU: 768 threads; gh weights from smem, gi in global ----
        if (n < 768) {
            int p = (n >= 384) ? 1 : 0;
            int j = n - p * 384;
            {
                const float* w = g_WihT + j;
                int kb = p * 128;
                float a0 = 0.f, a1 = 0.f, a2 = 0.f, a3 = 0.f,
                      a4 = 0.f, a5 = 0.f, a6 = 0.f, a7 = 0.f;
#pragma unroll 4
                for (int k = 0; k < 128; k += 8) {
                    a0 = fmaf(s_emb[kb + k + 0], w[(kb + k + 0) * 384], a0);
                    a1 = fmaf(s_emb[kb + k + 1], w[(kb + k + 1) * 384], a1);
                    a2 = fmaf(s_emb[kb + k + 2], w[(kb + k + 2) * 384], a2);
                    a3 = fmaf(s_emb[kb + k + 3], w[(kb + k + 3) * 384], a3);
                    a4 = fmaf(s_emb[kb + k + 4], w[(kb + k + 4) * 384], a4);
                    a5 = fmaf(s_emb[kb + k + 5], w[(kb + k + 5) * 384], a5);
                    a6 = fmaf(s_emb[kb + k + 6], w[(kb + k + 6) * 384], a6);
                    a7 = fmaf(s_emb[kb + k + 7], w[(kb + k + 7) * 384], a7);
                }
                s_part[p * 384 + j] = ((a0 + a1) + (a2 + a3)) + ((a4 + a5) + (a6 + a7));
            }
            BAR768();
            if (n < 384)
                g_gi[((b * Sn) + c) * 384 + n] = bih[n] + s_part[n] + s_part[384 + n];
            BAR768();
            for (int t2 = 0; t2 <= c; t2++) {
                // prefetch gi for this step (hidden behind gh matvec)
                float giv0 = 0.f, giv1 = 0.f, giv2 = 0.f;
                if (n < Hn) {
                    const float* gg = g_gi + ((b * Sn) + t2) * 384;
                    giv0 = gg[n]; giv1 = gg[Hn + n]; giv2 = gg[2 * Hn + n];
                }
                {
                    const float* w = s_whh + j;
                    int kb = p * 64;
                    float a0 = 0.f, a1 = 0.f, a2 = 0.f, a3 = 0.f,
                          a4 = 0.f, a5 = 0.f, a6 = 0.f, a7 = 0.f;
#pragma unroll 2
                    for (int k = 0; k < 64; k += 8) {
                        a0 = fmaf(s_hidden[kb + k + 0], w[(kb + k + 0) * 384], a0);
                        a1 = fmaf(s_hidden[kb + k + 1], w[(kb + k + 1) * 384], a1);
                        a2 = fmaf(s_hidden[kb + k + 2], w[(kb + k + 2) * 384], a2);
                        a3 = fmaf(s_hidden[kb + k + 3], w[(kb + k + 3) * 384], a3);
                        a4 = fmaf(s_hidden[kb + k + 4], w[(kb + k + 4) * 384], a4);
                        a5 = fmaf(s_hidden[kb + k + 5], w[(kb + k + 5) * 384], a5);
                        a6 = fmaf(s_hidden[kb + k + 6], w[(kb + k + 6) * 384], a6);
                        a7 = fmaf(s_hidden[kb + k + 7], w[(kb + k + 7) * 384], a7);
                    }
                    s_part[p * 384 + j] = ((a0 + a1) + (a2 + a3)) + ((a4 + a5) + (a6 + a7));
                }
                BAR768();
                if (n < Hn) {
                    float hr = bh0 + s_part[n] + s_part[384 + n];
                    float hz = bh1 + s_part[Hn + n] + s_part[384 + Hn + n];
                    float hn = bh2 + s_part[2 * Hn + n] + s_part[384 + 2 * Hn + n];
                    float r = sigm(giv0 + hr);
                    float z = sigm(giv1 + hz);
                    float nn = tanhf(giv2 + r * hn);
                    float hprev = s_hidden[n];
                    s_hidden[n] = (1.0f - z) * nn + z * hprev;
                }
                BAR768();
            }
            if (n < Hn) s_gctx[n] = s_hidden[n];
        }
        __syncthreads();
    }

    // cluster_adj = ones - eye
    if (n < Sn * Sn) {
        int i = n / Sn, j = n % Sn;
        out_ca[b * Sn * Sn + n] = (i == j) ? 0.0f : 1.0f;
    }
}

extern "C" void kernel_launch(void* const* d_in, const int* in_sizes, int n_in,
                              void* d_out, int out_size) {
    (void)in_sizes; (void)out_size;
    int k = (n_in >= 13) ? 3 : 2;
    const float* x   = (const float*)d_in[0];
    const float* adj = (const float*)d_in[1];
    const float* W1  = (const float*)d_in[k + 0];
    const float* b1  = (const float*)d_in[k + 1];
    const float* W2  = (const float*)d_in[k + 2];
    const float* b2  = (const float*)d_in[k + 3];
    const float* Wih = (const float*)d_in[k + 4];
    const float* Whh = (const float*)d_in[k + 5];
    const float* bih = (const float*)d_in[k + 6];
    const float* bhh = (const float*)d_in[k + 7];
    const float* Wc  = (const float*)d_in[k + 8];
    const float* bc  = (const float*)d_in[k + 9];

    // setting an attribute is idempotent & deterministic; required for >48KB smem
    cudaFuncSetAttribute(k_main, cudaFuncAttributeMaxDynamicSharedMemorySize, SMEM_BYTES);

    k_xw1<<<dim3(16, Bn), 256>>>(x, W1, b1);
    k_xmean<<<dim3(Bn, 8), 256>>>(x);
    k_transpose<<<(384 * 256 + 255) / 256, 256>>>(Wih, Whh);
    k_main<<<Bn, 1024, SMEM_BYTES>>>(x, adj, W1, W2, b2, bih, bhh, Wc, bc, (float*)d_out);
}

// round 16
// speedup vs baseline: 2.5592x; 1.1082x over previous
#include <cuda_runtime.h>
#include <math.h>
#include <stdint.h>

// Problem constants
#define Bn 16
#define Nn 1024
#define Dn 256
#define Hn 128
#define Sn 12     // MAX_CLUSTERS
#define CSn 16    // CSIZE
#define NEGV (-1e9f)

#define PARTITIONABLE 1

// ---------------- scratch ----------------
__device__ float g_XW1t[Bn * Hn * Nn];      // [b][h][n] = x@W1[:256] + b1
__device__ float g_WihT[Dn * 3 * Hn];       // [256][384]
__device__ float g_WhhT[Hn * 3 * Hn];       // [128][384]
__device__ float g_xpart[Bn][8][Dn];        // partial column sums of x
__device__ float g_gi[Bn * Sn * 3 * Hn];    // per-cluster input gates

// ---------------- Threefry2x32 (JAX-exact) ----------------
__device__ __forceinline__ uint2 tf2x32(unsigned k0, unsigned k1, unsigned x0, unsigned x1) {
    unsigned ks2 = k0 ^ k1 ^ 0x1BD11BDAu;
    x0 += k0; x1 += k1;
#define TFR(r) { x0 += x1; x1 = (x1 << (r)) | (x1 >> (32 - (r))); x1 ^= x0; }
    TFR(13) TFR(15) TFR(26) TFR(6)   x0 += k1;  x1 += ks2 + 1u;
    TFR(17) TFR(29) TFR(16) TFR(24)  x0 += ks2; x1 += k0 + 2u;
    TFR(13) TFR(15) TFR(26) TFR(6)   x0 += k0;  x1 += k1 + 3u;
    TFR(17) TFR(29) TFR(16) TFR(24)  x0 += k1;  x1 += ks2 + 4u;
    TFR(13) TFR(15) TFR(26) TFR(6)   x0 += ks2; x1 += k0 + 5u;
#undef TFR
    return make_uint2(x0, x1);
}

struct P2 { unsigned x, y; };
constexpr unsigned rotl_c(unsigned x, int r) { return (x << r) | (x >> (32 - r)); }
constexpr P2 tf_c(unsigned k0, unsigned k1, unsigned x0, unsigned x1) {
    unsigned ks2 = k0 ^ k1 ^ 0x1BD11BDAu;
    x0 += k0; x1 += k1;
    const int R0[4] = {13, 15, 26, 6};
    const int R1[4] = {17, 29, 16, 24};
    for (int i = 0; i < 5; i++) {
        for (int j = 0; j < 4; j++) {
            int r = (i % 2 == 0) ? R0[j] : R1[j];
            x0 += x1; x1 = rotl_c(x1, r); x1 ^= x0;
        }
        int a = (i + 1) % 3, bsel = (i + 2) % 3;
        unsigned inj0 = (a == 0) ? k0 : ((a == 1) ? k1 : ks2);
        unsigned inj1 = (bsel == 0) ? k0 : ((bsel == 1) ? k1 : ks2);
        x0 += inj0; x1 += inj1 + (unsigned)(i + 1);
    }
    return P2{x0, x1};
}

struct KeyTab { unsigned a[Sn * CSn]; unsigned b[Sn * CSn]; };
constexpr KeyTab mk_keys() {
    KeyTab t{};
    unsigned k0 = 0u, k1 = 42u;
    for (int i = 0; i < Sn * CSn; i++) {
#if PARTITIONABLE
        P2 nk = tf_c(k0, k1, 0u, 0u);
        P2 sk = tf_c(k0, k1, 0u, 1u);
        t.a[i] = sk.x; t.b[i] = sk.y;
        k0 = nk.x; k1 = nk.y;
#else
        P2 l0 = tf_c(k0, k1, 0u, 2u);
        P2 l1 = tf_c(k0, k1, 1u, 3u);
        t.a[i] = l0.y; t.b[i] = l1.y;
        k0 = l0.x; k1 = l1.x;
#endif
    }
    return t;
}
static constexpr KeyTab H_KEYS = mk_keys();
__constant__ KeyTab SELKEYS = H_KEYS;

__device__ __forceinline__ unsigned rand_bits(unsigned k0, unsigned k1, unsigned g) {
#if PARTITIONABLE
    uint2 o = tf2x32(k0, k1, 0u, g);
    return o.x ^ o.y;
#else
    const unsigned m = (Bn * Nn) / 2;
    if (g < m) { uint2 o = tf2x32(k0, k1, g, g + m); return o.x; }
    else       { uint2 o = tf2x32(k0, k1, g - m, g); return o.y; }
#endif
}

// Gumbel noise term (independent of logit)
__device__ __forceinline__ float gumbel_noise(unsigned k0, unsigned k1, int b, int node) {
    unsigned bits = rand_bits(k0, k1, (unsigned)((b << 10) + node));
    float u = __uint_as_float((bits >> 9) | 0x3f800000u) - 1.0f;
    float s1 = u + 1e-8f;
    float l1 = logf(s1);
    float s2 = (-l1) + 1e-8f;
    float l2 = logf(s2);
    return -l2;
}

__device__ __forceinline__ float gumbel_val(unsigned k0, unsigned k1, int b, int node,
                                            float logit) {
    return logit + gumbel_noise(k0, k1, b, node);
}

__device__ __forceinline__ unsigned long long packkey(float val, int node) {
    unsigned ub = __float_as_uint(val);
    unsigned ord = (ub & 0x80000000u) ? ~ub : (ub | 0x80000000u);
    return (((unsigned long long)ord) << 32) | (unsigned)(0xFFFFFFFFu - node);
}

__device__ __forceinline__ float sigm(float v) {
    return 0.5f * tanhf(0.5f * v) + 0.5f;
}

// ---------------- Kernel 1: tiled SGEMM ----------------
__global__ void __launch_bounds__(256) k_xw1(const float* __restrict__ x,
                                             const float* __restrict__ W1,
                                             const float* __restrict__ b1) {
    __shared__ float xs[64][33];
    __shared__ float ws[32][128];
    int tile = blockIdx.x;
    int b = blockIdx.y;
    int t = threadIdx.x;
    int n0 = tile * 64;
    int nl = t & 63;
    int jbase = (t >> 6) * 32;

    float acc[32];
#pragma unroll
    for (int i = 0; i < 32; i++) acc[i] = 0.f;

    for (int k0 = 0; k0 < Dn; k0 += 32) {
        for (int i = t; i < 64 * 32; i += 256) {
            int nn = i >> 5, kk = i & 31;
            xs[nn][kk] = x[((b << 10) + n0 + nn) * Dn + k0 + kk];
        }
        for (int i = t; i < 32 * 128; i += 256) {
            int kk = i >> 7, jj = i & 127;
            ws[kk][jj] = W1[(k0 + kk) * Hn + jj];
        }
        __syncthreads();
#pragma unroll 4
        for (int k = 0; k < 32; k++) {
            float xv = xs[nl][k];
            const float4* w4 = reinterpret_cast<const float4*>(&ws[k][jbase]);
#pragma unroll
            for (int i = 0; i < 8; i++) {
                float4 w = w4[i];
                acc[4 * i + 0] = fmaf(xv, w.x, acc[4 * i + 0]);
                acc[4 * i + 1] = fmaf(xv, w.y, acc[4 * i + 1]);
                acc[4 * i + 2] = fmaf(xv, w.z, acc[4 * i + 2]);
                acc[4 * i + 3] = fmaf(xv, w.w, acc[4 * i + 3]);
            }
        }
        __syncthreads();
    }
#pragma unroll
    for (int i = 0; i < 32; i++) {
        int j = jbase + i;
        g_XW1t[((b << 7) + j) * Nn + n0 + nl] = acc[i] + b1[j];
    }
}

// ---------------- Kernel 2: transpose GRU weights ----------------
__global__ void k_transpose(const float* __restrict__ Wih, const float* __restrict__ Whh) {
    int idx = blockIdx.x * blockDim.x + threadIdx.x;
    if (idx < 384 * 256) { int j = idx / 256, k = idx % 256; g_WihT[k * 384 + j] = Wih[idx]; }
    if (idx < 384 * 128) { int j = idx / 128, k = idx % 128; g_WhhT[k * 384 + j] = Whh[idx]; }
}

// ---------------- Kernel 3: xmean partials (deterministic) ----------------
__global__ void __launch_bounds__(256) k_xmean(const float* __restrict__ x) {
    int b = blockIdx.x, p = blockIdx.y;   // 16 x 8
    int t = threadIdx.x;                  // column 0..255
    const float* px = x + (((long)(b) << 10) + p * 128) * Dn + t;
    float a0 = 0.f, a1 = 0.f, a2 = 0.f, a3 = 0.f, a4 = 0.f, a5 = 0.f, a6 = 0.f, a7 = 0.f;
    for (int m = 0; m < 128; m += 8) {
        a0 += px[(m + 0) * Dn]; a1 += px[(m + 1) * Dn];
        a2 += px[(m + 2) * Dn]; a3 += px[(m + 3) * Dn];
        a4 += px[(m + 4) * Dn]; a5 += px[(m + 5) * Dn];
        a6 += px[(m + 6) * Dn]; a7 += px[(m + 7) * Dn];
    }
    g_xpart[b][p][t] = ((a0 + a1) + (a2 + a3)) + ((a4 + a5) + (a6 + a7));
}

#define BAR768() asm volatile("bar.sync 1, 768;" ::: "memory")

#define WHH_F (Hn * 3 * Hn)   // 49152 floats
#define PNCAP 224             // precomputed-noise candidate cap
// dynamic smem bytes: R15 layout (218448) + s_ccnt (4) + noise table (15*224*4)
#define SMEM_BYTES (218452 + 15 * PNCAP * 4)

// ---------------- Main kernel (R15 + block-wide grow-noise precompute) ----------------
__global__ void __launch_bounds__(1024) k_main(
    const float* __restrict__ x, const float* __restrict__ adj,
    const float* __restrict__ W1, const float* __restrict__ W2, const float* __restrict__ b2,
    const float* __restrict__ bih, const float* __restrict__ bhh,
    const float* __restrict__ Wc, const float* __restrict__ bc,
    float* __restrict__ out) {
    int b = blockIdx.x;
    int n = threadIdx.x;
    int lane = n & 31, wid = n >> 5;

    extern __shared__ float dsm[];
    float* s_whh   = dsm;                    // 49152
    float* s_logit = dsm + WHH_F;            // 1024
    float* s_ctx   = s_logit + Nn;           // 128
    float* s_gctx  = s_ctx + Hn;             // 128
    float* s_hidden= s_gctx + Hn;            // 128
    float* s_part  = s_hidden + Hn;          // 768
    float* s_emb   = s_part + 768;           // 256
    float* s_w2    = s_emb + Dn;             // 128
    unsigned char* s_avail = (unsigned char*)(s_w2 + Hn);
    unsigned char* s_mem   = s_avail + Nn;
    unsigned char* s_kmask = s_mem + Nn;
    int* s_clist = (int*)(s_kmask + Nn);
    int* s_flist = s_clist + Nn;
    unsigned long long* s_red = (unsigned long long*)(s_flist + Nn);
    int* s_mlist = (int*)(s_red + 32);
    int* s_fcnt = s_mlist + CSn + 1;
    int* s_mcnt = s_fcnt + 1;
    int* s_ccnt = s_mcnt + 1;
    float* s_gnoise = (float*)(s_ccnt + 1);  // [15][PNCAP]

    // load WhhT into smem (coalesced; one-time)
    for (int i = n; i < WHH_F; i += 1024) s_whh[i] = g_WhhT[i];

    s_avail[n] = 1;
    if (n < Dn) {
        float s = ((g_xpart[b][0][n] + g_xpart[b][1][n]) + (g_xpart[b][2][n] + g_xpart[b][3][n]))
                + ((g_xpart[b][4][n] + g_xpart[b][5][n]) + (g_xpart[b][6][n] + g_xpart[b][7][n]));
        s_emb[n] = s / 1024.0f;
    }
    if (n < Hn) s_w2[n] = W2[n];
    __syncthreads();
    if (n < Hn) {
        float a0 = 0.f, a1 = 0.f, a2 = 0.f, a3 = 0.f;
        for (int d = 0; d < Dn; d += 4) {
            a0 = fmaf(s_emb[d + 0], Wc[(d + 0) * Hn + n], a0);
            a1 = fmaf(s_emb[d + 1], Wc[(d + 1) * Hn + n], a1);
            a2 = fmaf(s_emb[d + 2], Wc[(d + 2) * Hn + n], a2);
            a3 = fmaf(s_emb[d + 3], Wc[(d + 3) * Hn + n], a3);
        }
        s_gctx[n] = bc[n] + ((a0 + a1) + (a2 + a3));
        s_hidden[n] = 0.f;
    }
    float b2v = b2[0];
    float bh0 = 0.f, bh1 = 0.f, bh2 = 0.f;
    if (n < Hn) { bh0 = bhh[n]; bh1 = bhh[Hn + n]; bh2 = bhh[2 * Hn + n]; }
    __syncthreads();

    float* out_cf = out;                       // [16][12][256]
    float* out_ca = out + Bn * Sn * Dn;        // [16][12][12]
    float* out_as = out_ca + Bn * Sn * Sn;     // [16][1024][12]

    const float* arow = adj + ((long)b << 20);

    for (int c = 0; c < Sn; c++) {
        s_mem[n] = 0;
        if (n == 0) *s_fcnt = 0;
        // ctx partials: 512 threads, 4 parts x 32 k
        if (n < 512) {
            int p = n >> 7, j = n & 127;
            int kb = Dn + p * 32;
            float a0 = 0.f, a1 = 0.f, a2 = 0.f, a3 = 0.f;
#pragma unroll
            for (int k = 0; k < 32; k += 4) {
                a0 = fmaf(s_gctx[p * 32 + k + 0], W1[(kb + k + 0) * Hn + j], a0);
                a1 = fmaf(s_gctx[p * 32 + k + 1], W1[(kb + k + 1) * Hn + j], a1);
                a2 = fmaf(s_gctx[p * 32 + k + 2], W1[(kb + k + 2) * Hn + j], a2);
                a3 = fmaf(s_gctx[p * 32 + k + 3], W1[(kb + k + 3) * Hn + j], a3);
            }
            s_part[p * 128 + j] = (a0 + a1) + (a2 + a3);
        }
        __syncthreads();
        if (n < Hn)
            s_ctx[n] = (s_part[n] + s_part[128 + n]) + (s_part[256 + n] + s_part[384 + n]);
        __syncthreads();

        // logits
        float mylogit;
        {
            float acc = 0.f;
            const float* px = g_XW1t + ((long)(b) << 7) * Nn + n;
#pragma unroll 8
            for (int j = 0; j < Hn; j++) {
                float v = px[j * Nn] + s_ctx[j];
                acc = fmaf(fmaxf(v, 0.f), s_w2[j], acc);
            }
            mylogit = acc + b2v;
            s_logit[n] = mylogit;
        }

        // seed selection
        {
            unsigned k0 = SELKEYS.a[c * CSn + 0], k1 = SELKEYS.b[c * CSn + 0];
            float val = NEGV;
            if (s_avail[n]) val = gumbel_val(k0, k1, b, n, mylogit);
            unsigned long long pk = packkey(val, n);
            for (int off = 16; off; off >>= 1) {
                unsigned long long o = __shfl_down_sync(0xffffffffu, pk, off);
                if (o > pk) pk = o;
            }
            if (lane == 0) s_red[wid] = pk;
        }
        __syncthreads();
        int sel, valid;
        {
            unsigned long long v2 = s_red[lane];
            for (int off = 16; off; off >>= 1) {
                unsigned long long o = __shfl_down_sync(0xffffffffu, v2, off);
                if (o > v2) v2 = o;
            }
            v2 = __shfl_sync(0xffffffffu, v2, 0);
            sel = (int)(0xFFFFFFFFu - (unsigned)(v2 & 0xFFFFFFFFu));
            unsigned ordv = (unsigned)(v2 >> 32);
            unsigned fb = (ordv & 0x80000000u) ? (ordv ^ 0x80000000u) : ~ordv;
            valid = (__uint_as_float(fb) > -1e8f) ? 1 : 0;
        }
        if (valid && n == sel) { s_avail[n] = 0; s_mem[n] = 1; }
        if (n == 0) {
            *s_mcnt = valid ? 1 : 0;
            if (valid) s_mlist[0] = sel;
        }

        // ---- 2-hop BFS ----
        bool nb1 = (arow[(sel << 10) + n] != 0.0f);
        bool reach1 = (n == sel) || nb1;
        if (nb1 && n != sel) { int p = atomicAdd(s_fcnt, 1); s_flist[p] = n; }
        __syncthreads();
        {
            int fc = *s_fcnt;
            bool rr = false;
            int f = 0;
            for (; f + 8 <= fc; f += 8) {
                float a0 = arow[(s_flist[f + 0] << 10) + n];
                float a1 = arow[(s_flist[f + 1] << 10) + n];
                float a2 = arow[(s_flist[f + 2] << 10) + n];
                float a3 = arow[(s_flist[f + 3] << 10) + n];
                float a4 = arow[(s_flist[f + 4] << 10) + n];
                float a5 = arow[(s_flist[f + 5] << 10) + n];
                float a6 = arow[(s_flist[f + 6] << 10) + n];
                float a7 = arow[(s_flist[f + 7] << 10) + n];
                rr = rr | (a0 != 0.f) | (a1 != 0.f) | (a2 != 0.f) | (a3 != 0.f)
                        | (a4 != 0.f) | (a5 != 0.f) | (a6 != 0.f) | (a7 != 0.f);
            }
            for (; f < fc; f++)
                rr = rr | (arow[(s_flist[f] << 10) + n] != 0.f);
            s_kmask[n] = (reach1 || rr) ? 1 : 0;
        }
        __syncthreads();

        // ---- candidate compaction (warp 0) ----
        if (wid == 0) {
            int cnt = 0;
            for (int base = 0; base < Nn; base += 32) {
                int node = base + lane;
                bool cd = s_avail[node] && s_kmask[node];
                unsigned mk = __ballot_sync(0xffffffffu, cd);
                if (cd) s_clist[cnt + __popc(mk & ((1u << lane) - 1u))] = node;
                cnt += __popc(mk);
            }
            if (lane == 0) *s_ccnt = cnt;
        }
        __syncthreads();

        // ---- block-wide noise precompute for grow steps (node-only dependence) ----
        int ccnt = *s_ccnt;
        int pn = (ccnt < PNCAP) ? ccnt : PNCAP;
        for (int idx = n; idx < 15 * pn; idx += 1024) {
            int ps = idx / pn, i = idx - ps * pn;
            int node = s_clist[i];
            s_gnoise[ps * PNCAP + i] =
                gumbel_noise(SELKEYS.a[c * CSn + 1 + ps], SELKEYS.b[c * CSn + 1 + ps],
                             b, node);
        }
        __syncthreads();

        // ---- grow steps s = 1..15: warp 0, smem noise ----
        if (wid == 0) {
            int cnt = ccnt;
            int aliveCnt = cnt;
            int mc = *s_mcnt;
            for (int s = 1; s < CSn; s++) {
                if (aliveCnt > 0) {
                    unsigned k0 = SELKEYS.a[c * CSn + s], k1 = SELKEYS.b[c * CSn + s];
                    unsigned long long pk =
                        (((unsigned long long)(~__float_as_uint(NEGV))) << 32);
                    for (int i = lane; i < cnt; i += 32) {
                        int node = s_clist[i];
                        if (node >= 0) {
                            float noise = (i < PNCAP) ? s_gnoise[(s - 1) * PNCAP + i]
                                                      : gumbel_noise(k0, k1, b, node);
                            float val = s_logit[node] + noise;
                            unsigned long long p2 = packkey(val, node);
                            if (p2 > pk) pk = p2;
                        }
                    }
                    for (int off = 16; off; off >>= 1) {
                        unsigned long long o = __shfl_xor_sync(0xffffffffu, pk, off);
                        if (o > pk) pk = o;
                    }
                    int node = (int)(0xFFFFFFFFu - (unsigned)(pk & 0xFFFFFFFFu));
                    for (int i = lane; i < cnt; i += 32)
                        if (s_clist[i] == node) s_clist[i] = -1;
                    if (lane == 0) {
                        s_avail[node] = 0; s_mem[node] = 1; s_mlist[mc] = node;
                    }
                    mc++;
                    aliveCnt--;
                }
            }
            if (lane == 0) {
                *s_mcnt = mc;
                for (int i = 1; i < mc; i++) {
                    int v = s_mlist[i], j = i - 1;
                    while (j >= 0 && s_mlist[j] > v) { s_mlist[j + 1] = s_mlist[j]; j--; }
                    s_mlist[j + 1] = v;
                }
            }
        }
        __syncthreads();

        // ---- cluster embedding (serial order-preserving sum) ----
        int mc = *s_mcnt;
        if (n < Dn) {
            float e = 0.f;
            for (int i = 0; i < mc; i++) e += x[((b << 10) + s_mlist[i]) * Dn + n];
            e = e / fmaxf((float)mc, 1.0f);
            s_emb[n] = e;
            out_cf[((b * Sn) + c) * Dn + n] = e;
        }
        out_as[((b << 10) + n) * Sn + c] = s_mem[n] ? 1.0f : 0.0f;
        __syncthreads();

        // ---- GRU: 768 threads; gh weights from smem, gi in global ----
        if (n < 768) {
            int p = (n >= 384) ? 1 : 0;
            int j = n - p * 384;
            {
                const float* w = g_WihT + j;
                int kb = p * 128;
                float a0 = 0.f, a1 = 0.f, a2 = 0.f, a3 = 0.f,
                      a4 = 0.f, a5 = 0.f, a6 = 0.f, a7 = 0.f;
#pragma unroll 4
                for (int k = 0; k < 128; k += 8) {
                    a0 = fmaf(s_emb[kb + k + 0], w[(kb + k + 0) * 384], a0);
                    a1 = fmaf(s_emb[kb + k + 1], w[(kb + k + 1) * 384], a1);
                    a2 = fmaf(s_emb[kb + k + 2], w[(kb + k + 2) * 384], a2);
                    a3 = fmaf(s_emb[kb + k + 3], w[(kb + k + 3) * 384], a3);
                    a4 = fmaf(s_emb[kb + k + 4], w[(kb + k + 4) * 384], a4);
                    a5 = fmaf(s_emb[kb + k + 5], w[(kb + k + 5) * 384], a5);
                    a6 = fmaf(s_emb[kb + k + 6], w[(kb + k + 6) * 384], a6);
                    a7 = fmaf(s_emb[kb + k + 7], w[(kb + k + 7) * 384], a7);
                }
                s_part[p * 384 + j] = ((a0 + a1) + (a2 + a3)) + ((a4 + a5) + (a6 + a7));
            }
            BAR768();
            if (n < 384)
                g_gi[((b * Sn) + c) * 384 + n] = bih[n] + s_part[n] + s_part[384 + n];
            BAR768();
            for (int t2 = 0; t2 <= c; t2++) {
                float giv0 = 0.f, giv1 = 0.f, giv2 = 0.f;
                if (n < Hn) {
                    const float* gg = g_gi + ((b * Sn) + t2) * 384;
                    giv0 = gg[n]; giv1 = gg[Hn + n]; giv2 = gg[2 * Hn + n];
                }
                {
                    const float* w = s_whh + j;
                    int kb = p * 64;
                    float a0 = 0.f, a1 = 0.f, a2 = 0.f, a3 = 0.f,
                          a4 = 0.f, a5 = 0.f, a6 = 0.f, a7 = 0.f;
#pragma unroll 2
                    for (int k = 0; k < 64; k += 8) {
                        a0 = fmaf(s_hidden[kb + k + 0], w[(kb + k + 0) * 384], a0);
                        a1 = fmaf(s_hidden[kb + k + 1], w[(kb + k + 1) * 384], a1);
                        a2 = fmaf(s_hidden[kb + k + 2], w[(kb + k + 2) * 384], a2);
                        a3 = fmaf(s_hidden[kb + k + 3], w[(kb + k + 3) * 384], a3);
                        a4 = fmaf(s_hidden[kb + k + 4], w[(kb + k + 4) * 384], a4);
                        a5 = fmaf(s_hidden[kb + k + 5], w[(kb + k + 5) * 384], a5);
                        a6 = fmaf(s_hidden[kb + k + 6], w[(kb + k + 6) * 384], a6);
                        a7 = fmaf(s_hidden[kb + k + 7], w[(kb + k + 7) * 384], a7);
                    }
                    s_part[p * 384 + j] = ((a0 + a1) + (a2 + a3)) + ((a4 + a5) + (a6 + a7));
                }
                BAR768();
                if (n < Hn) {
                    float hr = bh0 + s_part[n] + s_part[384 + n];
                    float hz = bh1 + s_part[Hn + n] + s_part[384 + Hn + n];
                    float hn = bh2 + s_part[2 * Hn + n] + s_part[384 + 2 * Hn + n];
                    float r = sigm(giv0 + hr);
                    float z = sigm(giv1 + hz);
                    float nn = tanhf(giv2 + r * hn);
                    float hprev = s_hidden[n];
                    s_hidden[n] = (1.0f - z) * nn + z * hprev;
                }
                BAR768();
            }
            if (n < Hn) s_gctx[n] = s_hidden[n];
        }
        __syncthreads();
    }

    // cluster_adj = ones - eye
    if (n < Sn * Sn) {
        int i = n / Sn, j = n % Sn;
        out_ca[b * Sn * Sn + n] = (i == j) ? 0.0f : 1.0f;
    }
}

extern "C" void kernel_launch(void* const* d_in, const int* in_sizes, int n_in,
                              void* d_out, int out_size) {
    (void)in_sizes; (void)out_size;
    int k = (n_in >= 13) ? 3 : 2;
    const float* x   = (const float*)d_in[0];
    const float* adj = (const float*)d_in[1];
    const float* W1  = (const float*)d_in[k + 0];
    const float* b1  = (const float*)d_in[k + 1];
    const float* W2  = (const float*)d_in[k + 2];
    const float* b2  = (const float*)d_in[k + 3];
    const float* Wih = (const float*)d_in[k + 4];
    const float* Whh = (const float*)d_in[k + 5];
    const float* bih = (const float*)d_in[k + 6];
    const float* bhh = (const float*)d_in[k + 7];
    const float* Wc  = (const float*)d_in[k + 8];
    const float* bc  = (const float*)d_in[k + 9];

    // idempotent; required for >48KB dynamic smem
    cudaFuncSetAttribute(k_main, cudaFuncAttributeMaxDynamicSharedMemorySize, SMEM_BYTES);

    k_xw1<<<dim3(16, Bn), 256>>>(x, W1, b1);
    k_xmean<<<dim3(Bn, 8), 256>>>(x);
    k_transpose<<<(384 * 256 + 255) / 256, 256>>>(Wih, Whh);
    k_main<<<Bn, 1024, SMEM_BYTES>>>(x, adj, W1, W2, b2, bih, bhh, Wc, bc, (float*)d_out);
}